// round 11
// baseline (speedup 1.0000x reference)
#include <cuda_runtime.h>
#include <cuda_bf16.h>
#include <math.h>

#define DEVI __device__ __forceinline__

__device__ float g_mu[16384];
__device__ float g_rstd[16384];
__device__ float g_q[2048 * 4096];     // [ng][o][pos]
__device__ float g_vs[2048 * 8];       // [ng][j][x,y]
__device__ float g_k[2048 * 256];      // [ng][j][o]
__device__ float g_v[2048 * 256];
__device__ float g_bias[2048 * 256];   // [ng][qi*4+j]
__device__ float g_att[512 * 16384];   // [c][n*64+qi]
__device__ unsigned g_w2bf[32768];     // fragment-ordered bf16x2 of cpb_w2 (8 mb32 x 16 kc x 32 lane x 8 u)
__device__ unsigned g_wqh[32768];      // wq hi  bf16x2: [g][kp=64][m=64]
__device__ unsigned g_wqm[32768];      // wq mid bf16x2

DEVI void mma16(float* c, const unsigned* a, unsigned b0, unsigned b1) {
    asm("mma.sync.aligned.m16n8k16.row.col.f32.bf16.bf16.f32 "
        "{%0,%1,%2,%3}, {%4,%5,%6,%7}, {%8,%9}, {%0,%1,%2,%3};"
        : "+f"(c[0]), "+f"(c[1]), "+f"(c[2]), "+f"(c[3])
        : "r"(a[0]), "r"(a[1]), "r"(a[2]), "r"(a[3]), "r"(b0), "r"(b1));
}
DEVI unsigned pack_bf2(float lo, float hi) {
    unsigned a = (unsigned)__bfloat16_as_ushort(__float2bfloat16_rn(lo));
    unsigned b = (unsigned)__bfloat16_as_ushort(__float2bfloat16_rn(hi));
    return a | (b << 16);
}
DEVI void split_bf(float v, unsigned short& h, unsigned short& m) {
    __nv_bfloat16 bh = __float2bfloat16_rn(v);
    float hv = __bfloat162float(bh);
    h = __bfloat16_as_ushort(bh);
    m = __bfloat16_as_ushort(__float2bfloat16_rn(v - hv));
}

// ---------------- K1: LayerNorm stats + w2/wq fragment packing ----------------
__global__ void __launch_bounds__(256) k_ln(const float* __restrict__ x,
                                           const float* __restrict__ w2,
                                           const float* __restrict__ wq) {
    int fi = blockIdx.x * 256 + threadIdx.x;
    if (fi < 32768) {
        int u = fi & 7, lane = (fi >> 3) & 31, kc = (fi >> 8) & 15, mb32 = fi >> 12;
        int tig = lane & 3, gid = lane >> 2;
        int mt = u >> 2, q = u & 3;
        int k2 = kc * 8 + tig + ((q & 2) ? 4 : 0);
        int m = mb32 * 32 + mt * 16 + gid + ((q & 1) ? 8 : 0);
        g_w2bf[fi] = pack_bf2(w2[(2 * k2) * 256 + m], w2[(2 * k2 + 1) * 256 + m]);
        int g = fi >> 12, kp = (fi >> 6) & 63, m2 = fi & 63;
        float v0 = wq[g * 8192 + m2 * 128 + 2 * kp];
        float v1 = wq[g * 8192 + m2 * 128 + 2 * kp + 1];
        unsigned short h0, mm0, h1, mm1;
        split_bf(v0, h0, mm0);
        split_bf(v1, h1, mm1);
        g_wqh[fi] = (unsigned)h0 | ((unsigned)h1 << 16);
        g_wqm[fi] = (unsigned)mm0 | ((unsigned)mm1 << 16);
    }
    int b = blockIdx.x >> 3, rp = blockIdx.x & 7;
    int t = threadIdx.x, pl = t & 31, w = t >> 5;
    const float* px = x + b * 262144 + rp * 32 + pl;
    float s = 0.f, q2 = 0.f;
    for (int c = w; c < 1024; c += 8) { float v = px[c * 256]; s += v; q2 += v * v; }
    __shared__ float rs[8][32], rq[8][32];
    rs[w][pl] = s; rq[w][pl] = q2;
    __syncthreads();
    if (t < 32) {
        float S = 0.f, Q = 0.f;
        #pragma unroll
        for (int i = 0; i < 8; i++) { S += rs[i][t]; Q += rq[i][t]; }
        float mu = S * (1.f / 1024.f);
        float var = Q * (1.f / 1024.f) - mu * mu;
        g_mu[b * 256 + rp * 32 + t] = mu;
        g_rstd[b * 256 + rp * 32 + t] = rsqrtf(var + 1e-6f);
    }
}

// ---------------- K2: Q projection via bf16 hi+mid 3-mma ----------------
__global__ void __launch_bounds__(256) k_qproj(
    const float* __restrict__ x, const float* __restrict__ lg,
    const float* __restrict__ lb) {
    __shared__ unsigned Xh[64 * 72], Xm[64 * 72];
    int ng = blockIdx.x, n = ng >> 3, g = ng & 7;
    int b = n & 63, quad = n >> 6, qh = quad >> 1, qw = quad & 1;
    int t = threadIdx.x;
    #pragma unroll 4
    for (int pass = 0; pass < 16; pass++) {
        int e = t + (pass << 8);
        int pos = e & 63, kp = e >> 6;
        int y = (qh << 3) + (pos >> 3), xx = (qw << 3) + (pos & 7);
        int cc0 = (g << 7) + 2 * kp;
        int mid = (b << 8) + y * 16 + xx;
        float mu = g_mu[mid], rstd = g_rstd[mid];
        float x0 = x[(b * 1024 + cc0) * 256 + y * 16 + xx];
        float x1 = x[(b * 1024 + cc0 + 1) * 256 + y * 16 + xx];
        float v0 = (x0 - mu) * rstd * __ldg(lg + cc0) + __ldg(lb + cc0);
        float v1 = (x1 - mu) * rstd * __ldg(lg + cc0 + 1) + __ldg(lb + cc0 + 1);
        unsigned short h0, m0v, h1, m1v;
        split_bf(v0, h0, m0v);
        split_bf(v1, h1, m1v);
        Xh[kp * 72 + pos] = (unsigned)h0 | ((unsigned)h1 << 16);
        Xm[kp * 72 + pos] = (unsigned)m0v | ((unsigned)m1v << 16);
    }
    __syncthreads();
    int lane = t & 31, w = t >> 5, gid = lane >> 2, tig = lane & 3;
    int wm = w >> 1, wn = w & 1;
    int m = wm * 16 + gid;
    const unsigned* qhp = g_wqh + (g << 12);
    const unsigned* qmp = g_wqm + (g << 12);
    float c[4][4];
    #pragma unroll
    for (int nt = 0; nt < 4; nt++) { c[nt][0] = 0.f; c[nt][1] = 0.f; c[nt][2] = 0.f; c[nt][3] = 0.f; }
    #pragma unroll
    for (int ks = 0; ks < 8; ks++) {
        int kp0 = ks * 8 + tig;
        unsigned ah[4], am[4];
        ah[0] = qhp[kp0 * 64 + m];       ah[1] = qhp[kp0 * 64 + m + 8];
        ah[2] = qhp[(kp0 + 4) * 64 + m]; ah[3] = qhp[(kp0 + 4) * 64 + m + 8];
        am[0] = qmp[kp0 * 64 + m];       am[1] = qmp[kp0 * 64 + m + 8];
        am[2] = qmp[(kp0 + 4) * 64 + m]; am[3] = qmp[(kp0 + 4) * 64 + m + 8];
        #pragma unroll
        for (int nt = 0; nt < 4; nt++) {
            int col = wn * 32 + nt * 8 + gid;
            unsigned bh0 = Xh[kp0 * 72 + col], bh1 = Xh[(kp0 + 4) * 72 + col];
            unsigned bm0 = Xm[kp0 * 72 + col], bm1 = Xm[(kp0 + 4) * 72 + col];
            mma16(c[nt], ah, bh0, bh1);
            mma16(c[nt], am, bh0, bh1);
            mma16(c[nt], ah, bm0, bm1);
        }
    }
    float* qo = g_q + ng * 4096;
    #pragma unroll
    for (int nt = 0; nt < 4; nt++)
        #pragma unroll
        for (int q = 0; q < 4; q++) {
            int o = wm * 16 + gid + ((q >> 1) << 3);
            int pos = wn * 32 + nt * 8 + tig * 2 + (q & 1);
            qo[o * 64 + pos] = c[nt][q];
        }
}

// ---------------- K3: offset head ----------------
__global__ void __launch_bounds__(64) k_off(
    const float* __restrict__ w1c, const float* __restrict__ b1c,
    const float* __restrict__ w2c) {
    __shared__ float qs3[64][65];
    __shared__ float contrib[64][8];
    __shared__ float tmp8[8];
    int ng = blockIdx.x, t = threadIdx.x;
    for (int p = 0; p < 64; p++) qs3[p][t] = g_q[ng * 4096 + p * 64 + t];
    float wr[36];
    #pragma unroll
    for (int u = 0; u < 36; u++) wr[u] = w1c[t * 36 + u];
    float bias = b1c[t], w2a = w2c[t], w2b = w2c[64 + t];
    __syncthreads();
    #pragma unroll
    for (int sy = 0; sy < 2; sy++)
    #pragma unroll
    for (int sx = 0; sx < 2; sx++) {
        float s = bias;
        #pragma unroll
        for (int ky = 0; ky < 6; ky++) {
            int iy = sy * 4 - 1 + ky;
            if (iy < 0 || iy > 7) continue;
            #pragma unroll
            for (int kx = 0; kx < 6; kx++) {
                int ix = sx * 4 - 1 + kx;
                if (ix < 0 || ix > 7) continue;
                s += wr[ky * 6 + kx] * qs3[t][iy * 8 + ix];
            }
        }
        float gl = 0.5f * s * (1.f + erff(s * 0.70710678118654752f));
        contrib[t][(sy * 2 + sx) * 2 + 0] = gl * w2a;
        contrib[t][(sy * 2 + sx) * 2 + 1] = gl * w2b;
    }
    __syncthreads();
    if (t < 8) {
        float s = 0.f;
        for (int cc = 0; cc < 64; cc++) s += contrib[cc][t];
        tmp8[t] = 4.f * tanhf(s);
    }
    __syncthreads();
    if (t < 4) {
        int sy = t >> 1, sx = t & 1;
        g_vs[ng * 8 + t * 2 + 0] = 2.f * ((float)sx + tmp8[t * 2 + 0]) - 1.f;
        g_vs[ng * 8 + t * 2 + 1] = 2.f * ((float)sy + tmp8[t * 2 + 1]) - 1.f;
    }
}

// ---------------- K4: bilinear KV gather + proj. grid 4096 = (ng, which) --------
__global__ void __launch_bounds__(256) k_kv(
    const float* __restrict__ x, const float* __restrict__ lg,
    const float* __restrict__ lb, const float* __restrict__ wk,
    const float* __restrict__ wv) {
    extern __shared__ float sm[];
    float* wks = sm;
    float* xp  = sm + 8256;
    float* kvs = sm + 16576;
    int bid = blockIdx.x;
    int ng = bid >> 1, which = bid & 1;
    int n = ng >> 3, g = ng & 7;
    int b = n & 63, quad = n >> 6, qh = quad >> 1, qw = quad & 1;
    int t = threadIdx.x;
    const float* wsrc = (which ? wv : wk) + (g << 13);
    #pragma unroll 4
    for (int p = 0; p < 32; p++) {
        int idx = t + (p << 8);
        { int o = idx >> 7, i = idx & 127;
          wks[o * 129 + i] = __ldg(wsrc + idx); }
        { int pos = idx & 63, i = idx >> 6;
          int y = (qh << 3) + (pos >> 3), xx = (qw << 3) + (pos & 7);
          int cc = (g << 7) + i;
          float raw = x[(b * 1024 + cc) * 256 + y * 16 + xx];
          int mid = (b << 8) + y * 16 + xx;
          xp[i * 65 + pos] = (raw - g_mu[mid]) * g_rstd[mid] * __ldg(lg + cc) + __ldg(lb + cc); }
    }
    __syncthreads();
    if (t < 128) {
        #pragma unroll
        for (int j = 0; j < 4; j++) {
            float vx = g_vs[ng * 8 + j * 2], vy = g_vs[ng * 8 + j * 2 + 1];
            float fx = ((vx + 1.f) * 8.f - 1.f) * 0.5f;
            float fy = ((vy + 1.f) * 8.f - 1.f) * 0.5f;
            float x0 = floorf(fx), y0 = floorf(fy);
            float wx1 = fx - x0, wy1 = fy - y0;
            float acc = 0.f;
            #pragma unroll
            for (int dy = 0; dy < 2; dy++)
            #pragma unroll
            for (int dx = 0; dx < 2; dx++) {
                float X = x0 + dx, Y = y0 + dy;
                if (X >= 0.f && X <= 7.f && Y >= 0.f && Y <= 7.f) {
                    float wgt = (dx ? wx1 : 1.f - wx1) * (dy ? wy1 : 1.f - wy1);
                    acc += wgt * xp[t * 65 + (int)Y * 8 + (int)X];
                }
            }
            kvs[t * 4 + j] = acc;
        }
    }
    __syncthreads();
    int o = t & 63, j = t >> 6;
    const float* wrow = wks + o * 129;
    float a = 0.f;
    #pragma unroll 4
    for (int i = 0; i < 128; i++) a += wrow[i] * kvs[i * 4 + j];
    ((which ? g_v : g_k) + (ng << 8))[j * 64 + o] = a;
}

// ---------------- K5: CPB MLP, bf16 mma, 2wm x 4wn retile, 2 blocks/SM ----------
// 8 warps: wn = w&3 (32-point quarter), wm = w>>2 (128 m-rows via mh loop).
// Per (mh,kc): 4 prefetched LDG.128 (A, 2 mb32), 8 LDS (B), 16 mmas (1:2 LDS:mma).
__global__ void __launch_bounds__(256, 2) k_cpb(
    const float* __restrict__ w1, const float* __restrict__ b1,
    const float* __restrict__ b2, const float* __restrict__ w3,
    const float* __restrict__ b3) {
    extern __shared__ float sm[];
    unsigned* H1p = (unsigned*)sm;
    float* w1s = sm + 17408;
    float* bx  = sm + 18176;
    float* by  = sm + 18432;
    float* part = sm + 18688;
    int ng = blockIdx.x, t = threadIdx.x;
    int lane = t & 31, w = t >> 5, gid = lane >> 2, tig = lane & 3;
    {
        w1s[t] = w1[t]; w1s[256 + t] = w1[256 + t]; w1s[512 + t] = b1[t];
        int qi = t >> 2, j = t & 3;
        float gqx = (2.f / 7.f) * (float)(qi & 7) - 1.f;
        float gqy = (2.f / 7.f) * (float)(qi >> 3) - 1.f;
        float px = gqx - g_vs[ng * 8 + j * 2], py = gqy - g_vs[ng * 8 + j * 2 + 1];
        bx[t] = copysignf(log1pf(fabsf(px)), px);
        by[t] = copysignf(log1pf(fabsf(py)), py);
    }
    int wn = w & 3, wm = w >> 2;
    float b3v = __ldg(b3);
    const uint4* wf = (const uint4*)g_w2bf;
    __syncthreads();
    for (int np = 0; np < 2; np++) {
        {   // fill H1 (bf16 pairs): 128 hidden-pair rows x 128 points
            int col = t & 127, pr0 = (t >> 7) << 6;
            float bxv = bx[np * 128 + col], byv = by[np * 128 + col];
            #pragma unroll 4
            for (int r = 0; r < 64; r++) {
                int pr = pr0 + r;
                float h0 = fmaxf(w1s[2 * pr] * bxv + w1s[256 + 2 * pr] * byv + w1s[512 + 2 * pr], 0.f);
                float h1 = fmaxf(w1s[2 * pr + 1] * bxv + w1s[256 + 2 * pr + 1] * byv + w1s[512 + 2 * pr + 1], 0.f);
                H1p[pr * 136 + col] = pack_bf2(h0, h1);
            }
        }
        __syncthreads();
        float colsum[8];
        #pragma unroll
        for (int i2 = 0; i2 < 8; i2++) colsum[i2] = 0.f;
        #pragma unroll
        for (int mh = 0; mh < 2; mh++) {
            int base = wm * 128 + mh * 64;       // first of 64 m-rows this mh
            int mb32a = base >> 5;               // two mb32 groups: mb32a, mb32a+1
            float c[4][4][4];
            #pragma unroll
            for (int mt = 0; mt < 4; mt++) {
                float ba = __ldg(b2 + base + mt * 16 + gid);
                float bb = __ldg(b2 + base + mt * 16 + gid + 8);
                #pragma unroll
                for (int nt = 0; nt < 4; nt++) {
                    c[mt][nt][0] = ba; c[mt][nt][1] = ba;
                    c[mt][nt][2] = bb; c[mt][nt][3] = bb;
                }
            }
            int fba = (mb32a * 512 + lane) * 2;
            int fbb = ((mb32a + 1) * 512 + lane) * 2;
            uint4 f0 = wf[fba], f1 = wf[fba + 1];
            uint4 f2 = wf[fbb], f3 = wf[fbb + 1];
            for (int kc = 0; kc < 16; kc++) {
                uint4 n0, n1, n2, n3;
                if (kc < 15) {
                    n0 = wf[fba + (kc + 1) * 64]; n1 = wf[fba + (kc + 1) * 64 + 1];
                    n2 = wf[fbb + (kc + 1) * 64]; n3 = wf[fbb + (kc + 1) * 64 + 1];
                }
                unsigned a0[4] = {f0.x, f0.y, f0.z, f0.w};
                unsigned a1[4] = {f1.x, f1.y, f1.z, f1.w};
                unsigned a2[4] = {f2.x, f2.y, f2.z, f2.w};
                unsigned a3[4] = {f3.x, f3.y, f3.z, f3.w};
                int rb0 = (kc * 8 + tig) * 136 + (wn << 5) + gid;
                int rb1 = rb0 + 544;
                #pragma unroll
                for (int nt = 0; nt < 4; nt++) {
                    unsigned b0 = H1p[rb0 + nt * 8];
                    unsigned bv = H1p[rb1 + nt * 8];
                    mma16(c[0][nt], a0, b0, bv);
                    mma16(c[1][nt], a1, b0, bv);
                    mma16(c[2][nt], a2, b0, bv);
                    mma16(c[3][nt], a3, b0, bv);
                }
                if (kc < 15) { f0 = n0; f1 = n1; f2 = n2; f3 = n3; }
            }
            #pragma unroll
            for (int mt = 0; mt < 4; mt++) {
                float w3a = __ldg(w3 + base + mt * 16 + gid);
                float w3b = __ldg(w3 + base + mt * 16 + gid + 8);
                #pragma unroll
                for (int nt = 0; nt < 4; nt++)
                    #pragma unroll
                    for (int q = 0; q < 2; q++)
                        colsum[nt * 2 + q] += w3a * fmaxf(c[mt][nt][q], 0.f)
                                            + w3b * fmaxf(c[mt][nt][2 + q], 0.f);
            }
        }
        #pragma unroll
        for (int off = 4; off < 32; off <<= 1)
            #pragma unroll
            for (int i2 = 0; i2 < 8; i2++)
                colsum[i2] += __shfl_xor_sync(0xffffffffu, colsum[i2], off);
        if (gid == 0) {
            #pragma unroll
            for (int i2 = 0; i2 < 8; i2++) {
                int nt = i2 >> 1, q = i2 & 1;
                part[wm * 128 + (wn << 5) + nt * 8 + tig * 2 + q] = colsum[i2];
            }
        }
        __syncthreads();
        if (t < 128) {
            g_bias[ng * 256 + np * 128 + t] = part[t] + part[128 + t] + b3v;
        }
        __syncthreads();
    }
}

// ---------------- K6: attention ----------------
__global__ void __launch_bounds__(256) k_att() {
    __shared__ float qs[64][65];
    __shared__ float ks4[4][65], vs4[4][65];
    __shared__ float att_s[64][5];
    int ng = blockIdx.x, n = ng >> 3, g = ng & 7;
    int t = threadIdx.x;
    #pragma unroll
    for (int p = 0; p < 16; p++) {
        int idx = t + (p << 8);
        qs[idx >> 6][idx & 63] = g_q[ng * 4096 + idx];
    }
    { int j = t >> 6, o = t & 63; ks4[j][o] = g_k[(ng << 8) + t]; vs4[j][o] = g_v[(ng << 8) + t]; }
    __syncthreads();
    int qi = t >> 2, j = t & 3;
    float s = 0.f;
    #pragma unroll 8
    for (int d = 0; d < 64; d++) s += qs[d][qi] * ks4[j][d];
    s = s * 0.125f + g_bias[(ng << 8) + t];
    float mx = fmaxf(s, __shfl_xor_sync(0xffffffffu, s, 1));
    mx = fmaxf(mx, __shfl_xor_sync(0xffffffffu, mx, 2));
    float e = __expf(s - mx);
    float sum = e;
    sum += __shfl_xor_sync(0xffffffffu, sum, 1);
    sum += __shfl_xor_sync(0xffffffffu, sum, 2);
    att_s[qi][j] = e / sum;
    __syncthreads();
    int qi2 = t & 63, dg = t >> 6;
    float a0 = att_s[qi2][0], a1 = att_s[qi2][1], a2 = att_s[qi2][2], a3 = att_s[qi2][3];
    #pragma unroll
    for (int dd = 0; dd < 16; dd++) {
        int d = (dg << 4) + dd;
        float r = a0 * vs4[0][d] + a1 * vs4[1][d] + a2 * vs4[2][d] + a3 * vs4[3][d];
        g_att[((g << 6) + d) * 16384 + (n << 6) + qi2] = r;
    }
}

// ---------------- K7: output projection, bf16 2-term split, pipelined ----------------
__global__ void __launch_bounds__(256) k_out(
    const float* __restrict__ ow, const float* __restrict__ ob,
    float* __restrict__ out) {
    __shared__ unsigned Ah[8 * 136], Am[8 * 136], Bh2[8 * 136], Bm2[8 * 136];
    int blk = blockIdx.x;
    int mb = (blk & 7) << 7, nb = (blk >> 3) << 7;
    int t = threadIdx.x, lane = t & 31, w = t >> 5;
    int gid = lane >> 2, tig = lane & 3;
    int mw = (w >> 2) << 6, nw = (w & 3) << 5;
    float c[4][4][4];
    #pragma unroll
    for (int mt = 0; mt < 4; mt++)
        #pragma unroll
        for (int nt = 0; nt < 4; nt++)
            #pragma unroll
            for (int q = 0; q < 4; q++) c[mt][nt][q] = 0.f;
    int ar = t >> 1, akq = (t & 1) << 3;
    int brp = t >> 5, bcq = (t & 31) << 2;
    float4 a0 = *(const float4*)(ow + (mb + ar) * 512 + akq);
    float4 a1 = *(const float4*)(ow + (mb + ar) * 512 + akq + 4);
    float4 bb0 = *(const float4*)(g_att + (2 * brp) * 16384 + nb + bcq);
    float4 bb1 = *(const float4*)(g_att + (2 * brp + 1) * 16384 + nb + bcq);
    for (int ck = 0; ck < 32; ck++) {
        __syncthreads();
        {
            float av[8] = {a0.x, a0.y, a0.z, a0.w, a1.x, a1.y, a1.z, a1.w};
            #pragma unroll
            for (int jj = 0; jj < 4; jj++) {
                unsigned short h0, m0v, h1, m1v;
                split_bf(av[jj * 2], h0, m0v);
                split_bf(av[jj * 2 + 1], h1, m1v);
                int p = (akq >> 1) + jj;
                Ah[p * 136 + ar] = (unsigned)h0 | ((unsigned)h1 << 16);
                Am[p * 136 + ar] = (unsigned)m0v | ((unsigned)m1v << 16);
            }
            float bv0[4] = {bb0.x, bb0.y, bb0.z, bb0.w};
            float bv1[4] = {bb1.x, bb1.y, bb1.z, bb1.w};
            #pragma unroll
            for (int jj = 0; jj < 4; jj++) {
                unsigned short h0, m0v, h1, m1v;
                split_bf(bv0[jj], h0, m0v);
                split_bf(bv1[jj], h1, m1v);
                Bh2[brp * 136 + bcq + jj] = (unsigned)h0 | ((unsigned)h1 << 16);
                Bm2[brp * 136 + bcq + jj] = (unsigned)m0v | ((unsigned)m1v << 16);
            }
        }
        __syncthreads();
        if (ck < 31) {
            int k0 = (ck + 1) << 4;
            a0 = *(const float4*)(ow + (mb + ar) * 512 + k0 + akq);
            a1 = *(const float4*)(ow + (mb + ar) * 512 + k0 + akq + 4);
            bb0 = *(const float4*)(g_att + (k0 + 2 * brp) * 16384 + nb + bcq);
            bb1 = *(const float4*)(g_att + (k0 + 2 * brp + 1) * 16384 + nb + bcq);
        }
        unsigned ah[4][4], am[4][4];
        #pragma unroll
        for (int mt = 0; mt < 4; mt++) {
            int m = mw + mt * 16 + gid;
            ah[mt][0] = Ah[tig * 136 + m];       am[mt][0] = Am[tig * 136 + m];
            ah[mt][1] = Ah[tig * 136 + m + 8];   am[mt][1] = Am[tig * 136 + m + 8];
            ah[mt][2] = Ah[(tig + 4) * 136 + m]; am[mt][2] = Am[(tig + 4) * 136 + m];
            ah[mt][3] = Ah[(tig + 4) * 136 + m + 8]; am[mt][3] = Am[(tig + 4) * 136 + m + 8];
        }
        #pragma unroll
        for (int nt = 0; nt < 4; nt++) {
            int col = nw + nt * 8 + gid;
            unsigned bh0 = Bh2[tig * 136 + col], bh1 = Bh2[(tig + 4) * 136 + col];
            unsigned bm0 = Bm2[tig * 136 + col], bm1 = Bm2[(tig + 4) * 136 + col];
            #pragma unroll
            for (int mt = 0; mt < 4; mt++) {
                mma16(c[mt][nt], ah[mt], bh0, bh1);
                mma16(c[mt][nt], am[mt], bh0, bh1);
                mma16(c[mt][nt], ah[mt], bm0, bm1);
            }
        }
    }
    #pragma unroll
    for (int mt = 0; mt < 4; mt++)
        #pragma unroll
        for (int nt = 0; nt < 4; nt++)
            #pragma unroll
            for (int q = 0; q < 4; q++) {
                int o = mb + mw + mt * 16 + gid + ((q >> 1) << 3);
                int col = nb + nw + nt * 8 + tig * 2 + (q & 1);
                int n = col >> 6, qi = col & 63;
                int b = n & 63, quad = n >> 6;
                int y = ((quad >> 1) << 3) + (qi >> 3);
                int xx = ((quad & 1) << 3) + (qi & 7);
                out[((b * 1024 + o) * 16 + y) * 16 + xx] = c[mt][nt][q] + __ldg(ob + o);
            }
}

extern "C" void kernel_launch(void* const* d_in, const int* in_sizes, int n_in,
                              void* d_out, int out_size) {
    const float* x      = (const float*)d_in[0];
    const float* ln_g   = (const float*)d_in[1];
    const float* ln_b   = (const float*)d_in[2];
    const float* wq     = (const float*)d_in[3];
    const float* wk     = (const float*)d_in[4];
    const float* wv     = (const float*)d_in[5];
    const float* off_w1 = (const float*)d_in[6];
    const float* off_b1 = (const float*)d_in[7];
    const float* off_w2 = (const float*)d_in[8];
    const float* cpb_w1 = (const float*)d_in[9];
    const float* cpb_b1 = (const float*)d_in[10];
    const float* cpb_w2 = (const float*)d_in[11];
    const float* cpb_b2 = (const float*)d_in[12];
    const float* cpb_w3 = (const float*)d_in[13];
    const float* cpb_b3 = (const float*)d_in[14];
    const float* out_w  = (const float*)d_in[15];
    const float* out_b  = (const float*)d_in[16];
    float* out = (float*)d_out;
    const int KV_SMEM  = 17088 * 4;   // 68352 B
    const int CPB_SMEM = 19200 * 4;   // 76800 B (2 blocks/SM)
    cudaFuncSetAttribute(k_kv,  cudaFuncAttributeMaxDynamicSharedMemorySize, KV_SMEM);
    cudaFuncSetAttribute(k_cpb, cudaFuncAttributeMaxDynamicSharedMemorySize, CPB_SMEM);
    k_ln<<<512, 256>>>(x, cpb_w2, wq);
    k_qproj<<<2048, 256>>>(x, ln_g, ln_b);
    k_off<<<2048, 64>>>(off_w1, off_b1, off_w2);
    k_cpb<<<2048, 256, CPB_SMEM>>>(cpb_w1, cpb_b1, cpb_b2, cpb_w3, cpb_b3);
    k_kv<<<4096, 256, KV_SMEM>>>(x, ln_g, ln_b, wk, wv);
    k_att<<<2048, 256>>>();
    k_out<<<1024, 256>>>(out_w, out_b, out);
}

// round 12
// speedup vs baseline: 1.0314x; 1.0314x over previous
#include <cuda_runtime.h>
#include <cuda_bf16.h>
#include <math.h>

#define DEVI __device__ __forceinline__

__device__ float g_mu[16384];
__device__ float g_rstd[16384];
__device__ float g_q[2048 * 4096];     // [ng][o][pos]
__device__ float g_vs[2048 * 8];       // [ng][j][x,y]
__device__ float g_k[2048 * 256];      // [ng][j][o]
__device__ float g_v[2048 * 256];
__device__ float g_bias[2048 * 256];   // [ng][qi*4+j]
__device__ float g_att[512 * 16384];   // [c][n*64+qi]
__device__ unsigned g_w2bf[32768];     // fragment-ordered bf16x2 of cpb_w2 (8 mb32 x 16 kc x 32 lane x 8 u)
__device__ unsigned g_wqh[32768];      // wq hi  bf16x2: [g][kp=64][m=64]
__device__ unsigned g_wqm[32768];      // wq mid bf16x2

DEVI void mma16(float* c, const unsigned* a, unsigned b0, unsigned b1) {
    asm("mma.sync.aligned.m16n8k16.row.col.f32.bf16.bf16.f32 "
        "{%0,%1,%2,%3}, {%4,%5,%6,%7}, {%8,%9}, {%0,%1,%2,%3};"
        : "+f"(c[0]), "+f"(c[1]), "+f"(c[2]), "+f"(c[3])
        : "r"(a[0]), "r"(a[1]), "r"(a[2]), "r"(a[3]), "r"(b0), "r"(b1));
}
DEVI unsigned pack_bf2(float lo, float hi) {
    unsigned a = (unsigned)__bfloat16_as_ushort(__float2bfloat16_rn(lo));
    unsigned b = (unsigned)__bfloat16_as_ushort(__float2bfloat16_rn(hi));
    return a | (b << 16);
}
DEVI void split_bf(float v, unsigned short& h, unsigned short& m) {
    __nv_bfloat16 bh = __float2bfloat16_rn(v);
    float hv = __bfloat162float(bh);
    h = __bfloat16_as_ushort(bh);
    m = __bfloat16_as_ushort(__float2bfloat16_rn(v - hv));
}

// ---------------- K1: LayerNorm stats + w2/wq fragment packing ----------------
__global__ void __launch_bounds__(256) k_ln(const float* __restrict__ x,
                                           const float* __restrict__ w2,
                                           const float* __restrict__ wq) {
    int fi = blockIdx.x * 256 + threadIdx.x;
    if (fi < 32768) {
        int u = fi & 7, lane = (fi >> 3) & 31, kc = (fi >> 8) & 15, mb32 = fi >> 12;
        int tig = lane & 3, gid = lane >> 2;
        int mt = u >> 2, q = u & 3;
        int k2 = kc * 8 + tig + ((q & 2) ? 4 : 0);
        int m = mb32 * 32 + mt * 16 + gid + ((q & 1) ? 8 : 0);
        g_w2bf[fi] = pack_bf2(w2[(2 * k2) * 256 + m], w2[(2 * k2 + 1) * 256 + m]);
        int g = fi >> 12, kp = (fi >> 6) & 63, m2 = fi & 63;
        float v0 = wq[g * 8192 + m2 * 128 + 2 * kp];
        float v1 = wq[g * 8192 + m2 * 128 + 2 * kp + 1];
        unsigned short h0, mm0, h1, mm1;
        split_bf(v0, h0, mm0);
        split_bf(v1, h1, mm1);
        g_wqh[fi] = (unsigned)h0 | ((unsigned)h1 << 16);
        g_wqm[fi] = (unsigned)mm0 | ((unsigned)mm1 << 16);
    }
    int b = blockIdx.x >> 3, rp = blockIdx.x & 7;
    int t = threadIdx.x, pl = t & 31, w = t >> 5;
    const float* px = x + b * 262144 + rp * 32 + pl;
    float s = 0.f, q2 = 0.f;
    for (int c = w; c < 1024; c += 8) { float v = px[c * 256]; s += v; q2 += v * v; }
    __shared__ float rs[8][32], rq[8][32];
    rs[w][pl] = s; rq[w][pl] = q2;
    __syncthreads();
    if (t < 32) {
        float S = 0.f, Q = 0.f;
        #pragma unroll
        for (int i = 0; i < 8; i++) { S += rs[i][t]; Q += rq[i][t]; }
        float mu = S * (1.f / 1024.f);
        float var = Q * (1.f / 1024.f) - mu * mu;
        g_mu[b * 256 + rp * 32 + t] = mu;
        g_rstd[b * 256 + rp * 32 + t] = rsqrtf(var + 1e-6f);
    }
}

// ---------------- K2: Q projection (bf16 3-mma) + fused offset head ----------------
__global__ void __launch_bounds__(256) k_qproj(
    const float* __restrict__ x, const float* __restrict__ lg,
    const float* __restrict__ lb, const float* __restrict__ ow1,
    const float* __restrict__ ob1, const float* __restrict__ ow2) {
    __shared__ unsigned Xh[64 * 72], Xm[64 * 72];
    __shared__ float tmp8[8];
    int ng = blockIdx.x, n = ng >> 3, g = ng & 7;
    int b = n & 63, quad = n >> 6, qh = quad >> 1, qw = quad & 1;
    int t = threadIdx.x;
    #pragma unroll 4
    for (int pass = 0; pass < 16; pass++) {
        int e = t + (pass << 8);
        int pos = e & 63, kp = e >> 6;
        int y = (qh << 3) + (pos >> 3), xx = (qw << 3) + (pos & 7);
        int cc0 = (g << 7) + 2 * kp;
        int mid = (b << 8) + y * 16 + xx;
        float mu = g_mu[mid], rstd = g_rstd[mid];
        float x0 = x[(b * 1024 + cc0) * 256 + y * 16 + xx];
        float x1 = x[(b * 1024 + cc0 + 1) * 256 + y * 16 + xx];
        float v0 = (x0 - mu) * rstd * __ldg(lg + cc0) + __ldg(lb + cc0);
        float v1 = (x1 - mu) * rstd * __ldg(lg + cc0 + 1) + __ldg(lb + cc0 + 1);
        unsigned short h0, m0v, h1, m1v;
        split_bf(v0, h0, m0v);
        split_bf(v1, h1, m1v);
        Xh[kp * 72 + pos] = (unsigned)h0 | ((unsigned)h1 << 16);
        Xm[kp * 72 + pos] = (unsigned)m0v | ((unsigned)m1v << 16);
    }
    __syncthreads();
    int lane = t & 31, w = t >> 5, gid = lane >> 2, tig = lane & 3;
    int wm = w >> 1, wn = w & 1;
    int m = wm * 16 + gid;
    const unsigned* qhp = g_wqh + (g << 12);
    const unsigned* qmp = g_wqm + (g << 12);
    float c[4][4];
    #pragma unroll
    for (int nt = 0; nt < 4; nt++) { c[nt][0] = 0.f; c[nt][1] = 0.f; c[nt][2] = 0.f; c[nt][3] = 0.f; }
    #pragma unroll
    for (int ks = 0; ks < 8; ks++) {
        int kp0 = ks * 8 + tig;
        unsigned ah[4], am[4];
        ah[0] = qhp[kp0 * 64 + m];       ah[1] = qhp[kp0 * 64 + m + 8];
        ah[2] = qhp[(kp0 + 4) * 64 + m]; ah[3] = qhp[(kp0 + 4) * 64 + m + 8];
        am[0] = qmp[kp0 * 64 + m];       am[1] = qmp[kp0 * 64 + m + 8];
        am[2] = qmp[(kp0 + 4) * 64 + m]; am[3] = qmp[(kp0 + 4) * 64 + m + 8];
        #pragma unroll
        for (int nt = 0; nt < 4; nt++) {
            int col = wn * 32 + nt * 8 + gid;
            unsigned bh0 = Xh[kp0 * 72 + col], bh1 = Xh[(kp0 + 4) * 72 + col];
            unsigned bm0 = Xm[kp0 * 72 + col], bm1 = Xm[(kp0 + 4) * 72 + col];
            mma16(c[nt], ah, bh0, bh1);
            mma16(c[nt], am, bh0, bh1);
            mma16(c[nt], ah, bm0, bm1);
        }
    }
    __syncthreads();   // all warps done reading Xh/Xm; reuse as q smem
    float* qf = (float*)Xh;       // [o][65] (16.6 KB < 18.4 KB)
    float* cb = (float*)Xm;       // contrib [o][8]
    float* qo = g_q + ng * 4096;
    #pragma unroll
    for (int nt = 0; nt < 4; nt++)
        #pragma unroll
        for (int q = 0; q < 4; q++) {
            int o = wm * 16 + gid + ((q >> 1) << 3);
            int pos = wn * 32 + nt * 8 + tig * 2 + (q & 1);
            qo[o * 64 + pos] = c[nt][q];
            qf[o * 65 + pos] = c[nt][q];
        }
    __syncthreads();
    // ---- fused offset head (threads 0..63, t = channel) ----
    if (t < 64) {
        float wr[36];
        #pragma unroll
        for (int u = 0; u < 36; u++) wr[u] = ow1[t * 36 + u];
        float bias = ob1[t], w2a = ow2[t], w2b = ow2[64 + t];
        #pragma unroll
        for (int sy = 0; sy < 2; sy++)
        #pragma unroll
        for (int sx = 0; sx < 2; sx++) {
            float s = bias;
            #pragma unroll
            for (int ky = 0; ky < 6; ky++) {
                int iy = sy * 4 - 1 + ky;
                if (iy < 0 || iy > 7) continue;
                #pragma unroll
                for (int kx = 0; kx < 6; kx++) {
                    int ix = sx * 4 - 1 + kx;
                    if (ix < 0 || ix > 7) continue;
                    s += wr[ky * 6 + kx] * qf[t * 65 + iy * 8 + ix];
                }
            }
            float gl = 0.5f * s * (1.f + erff(s * 0.70710678118654752f));
            cb[t * 8 + (sy * 2 + sx) * 2 + 0] = gl * w2a;
            cb[t * 8 + (sy * 2 + sx) * 2 + 1] = gl * w2b;
        }
    }
    __syncthreads();
    if (t < 8) {
        float s = 0.f;
        for (int cc = 0; cc < 64; cc++) s += cb[cc * 8 + t];
        tmp8[t] = 4.f * tanhf(s);
    }
    __syncthreads();
    if (t < 4) {
        int sy = t >> 1, sx = t & 1;
        g_vs[ng * 8 + t * 2 + 0] = 2.f * ((float)sx + tmp8[t * 2 + 0]) - 1.f;
        g_vs[ng * 8 + t * 2 + 1] = 2.f * ((float)sy + tmp8[t * 2 + 1]) - 1.f;
    }
}

// ---------------- K4: bilinear KV gather + proj. grid 4096 = (ng, which) --------
__global__ void __launch_bounds__(256) k_kv(
    const float* __restrict__ x, const float* __restrict__ lg,
    const float* __restrict__ lb, const float* __restrict__ wk,
    const float* __restrict__ wv) {
    extern __shared__ float sm[];
    float* wks = sm;
    float* xp  = sm + 8256;
    float* kvs = sm + 16576;
    int bid = blockIdx.x;
    int ng = bid >> 1, which = bid & 1;
    int n = ng >> 3, g = ng & 7;
    int b = n & 63, quad = n >> 6, qh = quad >> 1, qw = quad & 1;
    int t = threadIdx.x;
    const float* wsrc = (which ? wv : wk) + (g << 13);
    #pragma unroll 4
    for (int p = 0; p < 32; p++) {
        int idx = t + (p << 8);
        { int o = idx >> 7, i = idx & 127;
          wks[o * 129 + i] = __ldg(wsrc + idx); }
        { int pos = idx & 63, i = idx >> 6;
          int y = (qh << 3) + (pos >> 3), xx = (qw << 3) + (pos & 7);
          int cc = (g << 7) + i;
          float raw = x[(b * 1024 + cc) * 256 + y * 16 + xx];
          int mid = (b << 8) + y * 16 + xx;
          xp[i * 65 + pos] = (raw - g_mu[mid]) * g_rstd[mid] * __ldg(lg + cc) + __ldg(lb + cc); }
    }
    __syncthreads();
    if (t < 128) {
        #pragma unroll
        for (int j = 0; j < 4; j++) {
            float vx = g_vs[ng * 8 + j * 2], vy = g_vs[ng * 8 + j * 2 + 1];
            float fx = ((vx + 1.f) * 8.f - 1.f) * 0.5f;
            float fy = ((vy + 1.f) * 8.f - 1.f) * 0.5f;
            float x0 = floorf(fx), y0 = floorf(fy);
            float wx1 = fx - x0, wy1 = fy - y0;
            float acc = 0.f;
            #pragma unroll
            for (int dy = 0; dy < 2; dy++)
            #pragma unroll
            for (int dx = 0; dx < 2; dx++) {
                float X = x0 + dx, Y = y0 + dy;
                if (X >= 0.f && X <= 7.f && Y >= 0.f && Y <= 7.f) {
                    float wgt = (dx ? wx1 : 1.f - wx1) * (dy ? wy1 : 1.f - wy1);
                    acc += wgt * xp[t * 65 + (int)Y * 8 + (int)X];
                }
            }
            kvs[t * 4 + j] = acc;
        }
    }
    __syncthreads();
    int o = t & 63, j = t >> 6;
    const float* wrow = wks + o * 129;
    float a = 0.f;
    #pragma unroll 4
    for (int i = 0; i < 128; i++) a += wrow[i] * kvs[i * 4 + j];
    ((which ? g_v : g_k) + (ng << 8))[j * 64 + o] = a;
}

// ---------------- K5: CPB MLP (R10 config: 4wm x 2wn, mh loop, 2 blocks/SM) -----
__global__ void __launch_bounds__(256, 2) k_cpb(
    const float* __restrict__ w1, const float* __restrict__ b1,
    const float* __restrict__ b2, const float* __restrict__ w3,
    const float* __restrict__ b3) {
    extern __shared__ float sm[];
    unsigned* H1p = (unsigned*)sm;
    float* w1s = sm + 17408;
    float* bx  = sm + 18176;
    float* by  = sm + 18432;
    float* part = sm + 18688;
    int ng = blockIdx.x, t = threadIdx.x;
    int lane = t & 31, w = t >> 5, gid = lane >> 2, tig = lane & 3;
    {
        w1s[t] = w1[t]; w1s[256 + t] = w1[256 + t]; w1s[512 + t] = b1[t];
        int qi = t >> 2, j = t & 3;
        float gqx = (2.f / 7.f) * (float)(qi & 7) - 1.f;
        float gqy = (2.f / 7.f) * (float)(qi >> 3) - 1.f;
        float px = gqx - g_vs[ng * 8 + j * 2], py = gqy - g_vs[ng * 8 + j * 2 + 1];
        bx[t] = copysignf(log1pf(fabsf(px)), px);
        by[t] = copysignf(log1pf(fabsf(py)), py);
    }
    int wm = w >> 1, wn = w & 1;
    float b3v = __ldg(b3);
    const uint4* wf = (const uint4*)g_w2bf;
    __syncthreads();
    for (int np = 0; np < 2; np++) {
        {
            int col = t & 127, pr0 = (t >> 7) << 6;
            float bxv = bx[np * 128 + col], byv = by[np * 128 + col];
            #pragma unroll 4
            for (int r = 0; r < 64; r++) {
                int pr = pr0 + r;
                float h0 = fmaxf(w1s[2 * pr] * bxv + w1s[256 + 2 * pr] * byv + w1s[512 + 2 * pr], 0.f);
                float h1 = fmaxf(w1s[2 * pr + 1] * bxv + w1s[256 + 2 * pr + 1] * byv + w1s[512 + 2 * pr + 1], 0.f);
                H1p[pr * 136 + col] = pack_bf2(h0, h1);
            }
        }
        __syncthreads();
        float colsum[16];
        #pragma unroll
        for (int i2 = 0; i2 < 16; i2++) colsum[i2] = 0.f;
        #pragma unroll
        for (int mh = 0; mh < 2; mh++) {
            int mb32 = wm * 2 + mh;
            int m0 = mb32 << 5;
            float c[2][8][4];
            #pragma unroll
            for (int mt = 0; mt < 2; mt++) {
                float ba = __ldg(b2 + m0 + mt * 16 + gid);
                float bb = __ldg(b2 + m0 + mt * 16 + gid + 8);
                #pragma unroll
                for (int nt = 0; nt < 8; nt++) {
                    c[mt][nt][0] = ba; c[mt][nt][1] = ba;
                    c[mt][nt][2] = bb; c[mt][nt][3] = bb;
                }
            }
            int fbase = (mb32 * 512 + lane) * 2;
            uint4 f0 = wf[fbase], f1 = wf[fbase + 1];
            for (int kc = 0; kc < 16; kc++) {
                uint4 n0, n1;
                if (kc < 15) { n0 = wf[fbase + (kc + 1) * 64]; n1 = wf[fbase + (kc + 1) * 64 + 1]; }
                unsigned a0[4] = {f0.x, f0.y, f0.z, f0.w};
                unsigned a1[4] = {f1.x, f1.y, f1.z, f1.w};
                int rb0 = (kc * 8 + tig) * 136 + (wn << 6) + gid;
                int rb1 = rb0 + 4 * 136;
                #pragma unroll
                for (int nt = 0; nt < 8; nt++) {
                    unsigned b0 = H1p[rb0 + nt * 8];
                    unsigned bv = H1p[rb1 + nt * 8];
                    mma16(c[0][nt], a0, b0, bv);
                    mma16(c[1][nt], a1, b0, bv);
                }
                if (kc < 15) { f0 = n0; f1 = n1; }
            }
            float w3r0 = __ldg(w3 + m0 + gid),      w3r1 = __ldg(w3 + m0 + gid + 8);
            float w3r2 = __ldg(w3 + m0 + 16 + gid), w3r3 = __ldg(w3 + m0 + 24 + gid);
            #pragma unroll
            for (int nt = 0; nt < 8; nt++)
                #pragma unroll
                for (int q = 0; q < 2; q++)
                    colsum[nt * 2 + q] +=
                        w3r0 * fmaxf(c[0][nt][q], 0.f) + w3r1 * fmaxf(c[0][nt][2 + q], 0.f) +
                        w3r2 * fmaxf(c[1][nt][q], 0.f) + w3r3 * fmaxf(c[1][nt][2 + q], 0.f);
        }
        #pragma unroll
        for (int off = 4; off < 32; off <<= 1)
            #pragma unroll
            for (int i2 = 0; i2 < 16; i2++)
                colsum[i2] += __shfl_xor_sync(0xffffffffu, colsum[i2], off);
        if (gid == 0) {
            #pragma unroll
            for (int i2 = 0; i2 < 16; i2++)
                part[wm * 128 + (wn << 6) + (i2 >> 1) * 8 + tig * 2 + (i2 & 1)] = colsum[i2];
        }
        __syncthreads();
        if (t < 128) {
            float s = part[t] + part[128 + t] + part[256 + t] + part[384 + t];
            g_bias[ng * 256 + np * 128 + t] = s + b3v;
        }
        __syncthreads();
    }
}

// ---------------- K6: attention ----------------
__global__ void __launch_bounds__(256) k_att() {
    __shared__ float qs[64][65];
    __shared__ float ks4[4][65], vs4[4][65];
    __shared__ float att_s[64][5];
    int ng = blockIdx.x, n = ng >> 3, g = ng & 7;
    int t = threadIdx.x;
    #pragma unroll
    for (int p = 0; p < 16; p++) {
        int idx = t + (p << 8);
        qs[idx >> 6][idx & 63] = g_q[ng * 4096 + idx];
    }
    { int j = t >> 6, o = t & 63; ks4[j][o] = g_k[(ng << 8) + t]; vs4[j][o] = g_v[(ng << 8) + t]; }
    __syncthreads();
    int qi = t >> 2, j = t & 3;
    float s = 0.f;
    #pragma unroll 8
    for (int d = 0; d < 64; d++) s += qs[d][qi] * ks4[j][d];
    s = s * 0.125f + g_bias[(ng << 8) + t];
    float mx = fmaxf(s, __shfl_xor_sync(0xffffffffu, s, 1));
    mx = fmaxf(mx, __shfl_xor_sync(0xffffffffu, mx, 2));
    float e = __expf(s - mx);
    float sum = e;
    sum += __shfl_xor_sync(0xffffffffu, sum, 1);
    sum += __shfl_xor_sync(0xffffffffu, sum, 2);
    att_s[qi][j] = e / sum;
    __syncthreads();
    int qi2 = t & 63, dg = t >> 6;
    float a0 = att_s[qi2][0], a1 = att_s[qi2][1], a2 = att_s[qi2][2], a3 = att_s[qi2][3];
    #pragma unroll
    for (int dd = 0; dd < 16; dd++) {
        int d = (dg << 4) + dd;
        float r = a0 * vs4[0][d] + a1 * vs4[1][d] + a2 * vs4[2][d] + a3 * vs4[3][d];
        g_att[((g << 6) + d) * 16384 + (n << 6) + qi2] = r;
    }
}

// ---------------- K7: output projection, bf16 2-term split, pipelined ----------------
__global__ void __launch_bounds__(256) k_out(
    const float* __restrict__ ow, const float* __restrict__ ob,
    float* __restrict__ out) {
    __shared__ unsigned Ah[8 * 136], Am[8 * 136], Bh2[8 * 136], Bm2[8 * 136];
    int blk = blockIdx.x;
    int mb = (blk & 7) << 7, nb = (blk >> 3) << 7;
    int t = threadIdx.x, lane = t & 31, w = t >> 5;
    int gid = lane >> 2, tig = lane & 3;
    int mw = (w >> 2) << 6, nw = (w & 3) << 5;
    float c[4][4][4];
    #pragma unroll
    for (int mt = 0; mt < 4; mt++)
        #pragma unroll
        for (int nt = 0; nt < 4; nt++)
            #pragma unroll
            for (int q = 0; q < 4; q++) c[mt][nt][q] = 0.f;
    int ar = t >> 1, akq = (t & 1) << 3;
    int brp = t >> 5, bcq = (t & 31) << 2;
    float4 a0 = *(const float4*)(ow + (mb + ar) * 512 + akq);
    float4 a1 = *(const float4*)(ow + (mb + ar) * 512 + akq + 4);
    float4 bb0 = *(const float4*)(g_att + (2 * brp) * 16384 + nb + bcq);
    float4 bb1 = *(const float4*)(g_att + (2 * brp + 1) * 16384 + nb + bcq);
    for (int ck = 0; ck < 32; ck++) {
        __syncthreads();
        {
            float av[8] = {a0.x, a0.y, a0.z, a0.w, a1.x, a1.y, a1.z, a1.w};
            #pragma unroll
            for (int jj = 0; jj < 4; jj++) {
                unsigned short h0, m0v, h1, m1v;
                split_bf(av[jj * 2], h0, m0v);
                split_bf(av[jj * 2 + 1], h1, m1v);
                int p = (akq >> 1) + jj;
                Ah[p * 136 + ar] = (unsigned)h0 | ((unsigned)h1 << 16);
                Am[p * 136 + ar] = (unsigned)m0v | ((unsigned)m1v << 16);
            }
            float bv0[4] = {bb0.x, bb0.y, bb0.z, bb0.w};
            float bv1[4] = {bb1.x, bb1.y, bb1.z, bb1.w};
            #pragma unroll
            for (int jj = 0; jj < 4; jj++) {
                unsigned short h0, m0v, h1, m1v;
                split_bf(bv0[jj], h0, m0v);
                split_bf(bv1[jj], h1, m1v);
                Bh2[brp * 136 + bcq + jj] = (unsigned)h0 | ((unsigned)h1 << 16);
                Bm2[brp * 136 + bcq + jj] = (unsigned)m0v | ((unsigned)m1v << 16);
            }
        }
        __syncthreads();
        if (ck < 31) {
            int k0 = (ck + 1) << 4;
            a0 = *(const float4*)(ow + (mb + ar) * 512 + k0 + akq);
            a1 = *(const float4*)(ow + (mb + ar) * 512 + k0 + akq + 4);
            bb0 = *(const float4*)(g_att + (k0 + 2 * brp) * 16384 + nb + bcq);
            bb1 = *(const float4*)(g_att + (k0 + 2 * brp + 1) * 16384 + nb + bcq);
        }
        unsigned ah[4][4], am[4][4];
        #pragma unroll
        for (int mt = 0; mt < 4; mt++) {
            int m = mw + mt * 16 + gid;
            ah[mt][0] = Ah[tig * 136 + m];       am[mt][0] = Am[tig * 136 + m];
            ah[mt][1] = Ah[tig * 136 + m + 8];   am[mt][1] = Am[tig * 136 + m + 8];
            ah[mt][2] = Ah[(tig + 4) * 136 + m]; am[mt][2] = Am[(tig + 4) * 136 + m];
            ah[mt][3] = Ah[(tig + 4) * 136 + m + 8]; am[mt][3] = Am[(tig + 4) * 136 + m + 8];
        }
        #pragma unroll
        for (int nt = 0; nt < 4; nt++) {
            int col = nw + nt * 8 + gid;
            unsigned bh0 = Bh2[tig * 136 + col], bh1 = Bh2[(tig + 4) * 136 + col];
            unsigned bm0 = Bm2[tig * 136 + col], bm1 = Bm2[(tig + 4) * 136 + col];
            #pragma unroll
            for (int mt = 0; mt < 4; mt++) {
                mma16(c[mt][nt], ah[mt], bh0, bh1);
                mma16(c[mt][nt], am[mt], bh0, bh1);
                mma16(c[mt][nt], ah[mt], bm0, bm1);
            }
        }
    }
    #pragma unroll
    for (int mt = 0; mt < 4; mt++)
        #pragma unroll
        for (int nt = 0; nt < 4; nt++)
            #pragma unroll
            for (int q = 0; q < 4; q++) {
                int o = mb + mw + mt * 16 + gid + ((q >> 1) << 3);
                int col = nb + nw + nt * 8 + tig * 2 + (q & 1);
                int n = col >> 6, qi = col & 63;
                int b = n & 63, quad = n >> 6;
                int y = ((quad >> 1) << 3) + (qi >> 3);
                int xx = ((quad & 1) << 3) + (qi & 7);
                out[((b * 1024 + o) * 16 + y) * 16 + xx] = c[mt][nt][q] + __ldg(ob + o);
            }
}

extern "C" void kernel_launch(void* const* d_in, const int* in_sizes, int n_in,
                              void* d_out, int out_size) {
    const float* x      = (const float*)d_in[0];
    const float* ln_g   = (const float*)d_in[1];
    const float* ln_b   = (const float*)d_in[2];
    const float* wq     = (const float*)d_in[3];
    const float* wk     = (const float*)d_in[4];
    const float* wv     = (const float*)d_in[5];
    const float* off_w1 = (const float*)d_in[6];
    const float* off_b1 = (const float*)d_in[7];
    const float* off_w2 = (const float*)d_in[8];
    const float* cpb_w1 = (const float*)d_in[9];
    const float* cpb_b1 = (const float*)d_in[10];
    const float* cpb_w2 = (const float*)d_in[11];
    const float* cpb_b2 = (const float*)d_in[12];
    const float* cpb_w3 = (const float*)d_in[13];
    const float* cpb_b3 = (const float*)d_in[14];
    const float* out_w  = (const float*)d_in[15];
    const float* out_b  = (const float*)d_in[16];
    float* out = (float*)d_out;
    const int KV_SMEM  = 17088 * 4;   // 68352 B
    const int CPB_SMEM = 19200 * 4;   // 76800 B (2 blocks/SM)
    cudaFuncSetAttribute(k_kv,  cudaFuncAttributeMaxDynamicSharedMemorySize, KV_SMEM);
    cudaFuncSetAttribute(k_cpb, cudaFuncAttributeMaxDynamicSharedMemorySize, CPB_SMEM);
    k_ln<<<512, 256>>>(x, cpb_w2, wq);
    k_qproj<<<2048, 256>>>(x, ln_g, ln_b, off_w1, off_b1, off_w2);
    k_cpb<<<2048, 256, CPB_SMEM>>>(cpb_w1, cpb_b1, cpb_b2, cpb_w3, cpb_b3);
    k_kv<<<4096, 256, KV_SMEM>>>(x, ln_g, ln_b, wk, wv);
    k_att<<<2048, 256>>>();
    k_out<<<1024, 256>>>(out_w, out_b, out);
}

// round 13
// speedup vs baseline: 1.1049x; 1.0713x over previous
#include <cuda_runtime.h>
#include <cuda_bf16.h>
#include <math.h>

#define DEVI __device__ __forceinline__

__device__ float g_mu[16384];
__device__ float g_rstd[16384];
__device__ float g_q[2048 * 4096];     // [ng][o][pos]
__device__ float g_vs[2048 * 8];       // [ng][j][x,y]
__device__ float g_k[2048 * 256];      // [ng][j][o]
__device__ float g_v[2048 * 256];
__device__ float g_bias[2048 * 256];   // [ng][qi*4+j]
__device__ float g_att[512 * 16384];   // [c][n*64+qi]
__device__ unsigned g_w2bf[32768];     // fragment-ordered bf16x2 of cpb_w2 (8 mb32 x 16 kc x 32 lane x 8 u)
__device__ unsigned g_wqh[32768];      // wq hi  bf16x2: [g][kp=64][m=64]
__device__ unsigned g_wqm[32768];      // wq mid bf16x2

DEVI void mma16(float* c, const unsigned* a, unsigned b0, unsigned b1) {
    asm("mma.sync.aligned.m16n8k16.row.col.f32.bf16.bf16.f32 "
        "{%0,%1,%2,%3}, {%4,%5,%6,%7}, {%8,%9}, {%0,%1,%2,%3};"
        : "+f"(c[0]), "+f"(c[1]), "+f"(c[2]), "+f"(c[3])
        : "r"(a[0]), "r"(a[1]), "r"(a[2]), "r"(a[3]), "r"(b0), "r"(b1));
}
DEVI unsigned pack_bf2(float lo, float hi) {
    unsigned a = (unsigned)__bfloat16_as_ushort(__float2bfloat16_rn(lo));
    unsigned b = (unsigned)__bfloat16_as_ushort(__float2bfloat16_rn(hi));
    return a | (b << 16);
}
DEVI void split_bf(float v, unsigned short& h, unsigned short& m) {
    __nv_bfloat16 bh = __float2bfloat16_rn(v);
    float hv = __bfloat162float(bh);
    h = __bfloat16_as_ushort(bh);
    m = __bfloat16_as_ushort(__float2bfloat16_rn(v - hv));
}

// ---------------- K1: LayerNorm stats + w2/wq fragment packing ----------------
__global__ void __launch_bounds__(256) k_ln(const float* __restrict__ x,
                                           const float* __restrict__ w2,
                                           const float* __restrict__ wq) {
    int fi = blockIdx.x * 256 + threadIdx.x;
    if (fi < 32768) {
        int u = fi & 7, lane = (fi >> 3) & 31, kc = (fi >> 8) & 15, mb32 = fi >> 12;
        int tig = lane & 3, gid = lane >> 2;
        int mt = u >> 2, q = u & 3;
        int k2 = kc * 8 + tig + ((q & 2) ? 4 : 0);
        int m = mb32 * 32 + mt * 16 + gid + ((q & 1) ? 8 : 0);
        g_w2bf[fi] = pack_bf2(w2[(2 * k2) * 256 + m], w2[(2 * k2 + 1) * 256 + m]);
        int g = fi >> 12, kp = (fi >> 6) & 63, m2 = fi & 63;
        float v0 = wq[g * 8192 + m2 * 128 + 2 * kp];
        float v1 = wq[g * 8192 + m2 * 128 + 2 * kp + 1];
        unsigned short h0, mm0, h1, mm1;
        split_bf(v0, h0, mm0);
        split_bf(v1, h1, mm1);
        g_wqh[fi] = (unsigned)h0 | ((unsigned)h1 << 16);
        g_wqm[fi] = (unsigned)mm0 | ((unsigned)mm1 << 16);
    }
    int b = blockIdx.x >> 3, rp = blockIdx.x & 7;
    int t = threadIdx.x, pl = t & 31, w = t >> 5;
    const float* px = x + b * 262144 + rp * 32 + pl;
    float s = 0.f, q2 = 0.f;
    for (int c = w; c < 1024; c += 8) { float v = px[c * 256]; s += v; q2 += v * v; }
    __shared__ float rs[8][32], rq[8][32];
    rs[w][pl] = s; rq[w][pl] = q2;
    __syncthreads();
    if (t < 32) {
        float S = 0.f, Q = 0.f;
        #pragma unroll
        for (int i = 0; i < 8; i++) { S += rs[i][t]; Q += rq[i][t]; }
        float mu = S * (1.f / 1024.f);
        float var = Q * (1.f / 1024.f) - mu * mu;
        g_mu[b * 256 + rp * 32 + t] = mu;
        g_rstd[b * 256 + rp * 32 + t] = rsqrtf(var + 1e-6f);
    }
}

// ---------------- K2: Q projection (bf16 3-mma) + fused offset head ----------------
__global__ void __launch_bounds__(256) k_qproj(
    const float* __restrict__ x, const float* __restrict__ lg,
    const float* __restrict__ lb, const float* __restrict__ ow1,
    const float* __restrict__ ob1, const float* __restrict__ ow2) {
    __shared__ unsigned Xh[64 * 72], Xm[64 * 72];
    __shared__ float tmp8[8];
    int ng = blockIdx.x, n = ng >> 3, g = ng & 7;
    int b = n & 63, quad = n >> 6, qh = quad >> 1, qw = quad & 1;
    int t = threadIdx.x;
    #pragma unroll 4
    for (int pass = 0; pass < 16; pass++) {
        int e = t + (pass << 8);
        int pos = e & 63, kp = e >> 6;
        int y = (qh << 3) + (pos >> 3), xx = (qw << 3) + (pos & 7);
        int cc0 = (g << 7) + 2 * kp;
        int mid = (b << 8) + y * 16 + xx;
        float mu = g_mu[mid], rstd = g_rstd[mid];
        float x0 = x[(b * 1024 + cc0) * 256 + y * 16 + xx];
        float x1 = x[(b * 1024 + cc0 + 1) * 256 + y * 16 + xx];
        float v0 = (x0 - mu) * rstd * __ldg(lg + cc0) + __ldg(lb + cc0);
        float v1 = (x1 - mu) * rstd * __ldg(lg + cc0 + 1) + __ldg(lb + cc0 + 1);
        unsigned short h0, m0v, h1, m1v;
        split_bf(v0, h0, m0v);
        split_bf(v1, h1, m1v);
        Xh[kp * 72 + pos] = (unsigned)h0 | ((unsigned)h1 << 16);
        Xm[kp * 72 + pos] = (unsigned)m0v | ((unsigned)m1v << 16);
    }
    __syncthreads();
    int lane = t & 31, w = t >> 5, gid = lane >> 2, tig = lane & 3;
    int wm = w >> 1, wn = w & 1;
    int m = wm * 16 + gid;
    const unsigned* qhp = g_wqh + (g << 12);
    const unsigned* qmp = g_wqm + (g << 12);
    float c[4][4];
    #pragma unroll
    for (int nt = 0; nt < 4; nt++) { c[nt][0] = 0.f; c[nt][1] = 0.f; c[nt][2] = 0.f; c[nt][3] = 0.f; }
    #pragma unroll
    for (int ks = 0; ks < 8; ks++) {
        int kp0 = ks * 8 + tig;
        unsigned ah[4], am[4];
        ah[0] = qhp[kp0 * 64 + m];       ah[1] = qhp[kp0 * 64 + m + 8];
        ah[2] = qhp[(kp0 + 4) * 64 + m]; ah[3] = qhp[(kp0 + 4) * 64 + m + 8];
        am[0] = qmp[kp0 * 64 + m];       am[1] = qmp[kp0 * 64 + m + 8];
        am[2] = qmp[(kp0 + 4) * 64 + m]; am[3] = qmp[(kp0 + 4) * 64 + m + 8];
        #pragma unroll
        for (int nt = 0; nt < 4; nt++) {
            int col = wn * 32 + nt * 8 + gid;
            unsigned bh0 = Xh[kp0 * 72 + col], bh1 = Xh[(kp0 + 4) * 72 + col];
            unsigned bm0 = Xm[kp0 * 72 + col], bm1 = Xm[(kp0 + 4) * 72 + col];
            mma16(c[nt], ah, bh0, bh1);
            mma16(c[nt], am, bh0, bh1);
            mma16(c[nt], ah, bm0, bm1);
        }
    }
    __syncthreads();   // all warps done reading Xh/Xm; reuse as q smem
    float* qf = (float*)Xh;       // [o][65]
    float* cb = (float*)Xm;       // contrib [o][8]
    float* qo = g_q + ng * 4096;
    #pragma unroll
    for (int nt = 0; nt < 4; nt++)
        #pragma unroll
        for (int q = 0; q < 4; q++) {
            int o = wm * 16 + gid + ((q >> 1) << 3);
            int pos = wn * 32 + nt * 8 + tig * 2 + (q & 1);
            qo[o * 64 + pos] = c[nt][q];
            qf[o * 65 + pos] = c[nt][q];
        }
    __syncthreads();
    if (t < 64) {
        float wr[36];
        #pragma unroll
        for (int u = 0; u < 36; u++) wr[u] = ow1[t * 36 + u];
        float bias = ob1[t], w2a = ow2[t], w2b = ow2[64 + t];
        #pragma unroll
        for (int sy = 0; sy < 2; sy++)
        #pragma unroll
        for (int sx = 0; sx < 2; sx++) {
            float s = bias;
            #pragma unroll
            for (int ky = 0; ky < 6; ky++) {
                int iy = sy * 4 - 1 + ky;
                if (iy < 0 || iy > 7) continue;
                #pragma unroll
                for (int kx = 0; kx < 6; kx++) {
                    int ix = sx * 4 - 1 + kx;
                    if (ix < 0 || ix > 7) continue;
                    s += wr[ky * 6 + kx] * qf[t * 65 + iy * 8 + ix];
                }
            }
            float gl = 0.5f * s * (1.f + erff(s * 0.70710678118654752f));
            cb[t * 8 + (sy * 2 + sx) * 2 + 0] = gl * w2a;
            cb[t * 8 + (sy * 2 + sx) * 2 + 1] = gl * w2b;
        }
    }
    __syncthreads();
    if (t < 8) {
        float s = 0.f;
        for (int cc = 0; cc < 64; cc++) s += cb[cc * 8 + t];
        tmp8[t] = 4.f * tanhf(s);
    }
    __syncthreads();
    if (t < 4) {
        int sy = t >> 1, sx = t & 1;
        g_vs[ng * 8 + t * 2 + 0] = 2.f * ((float)sx + tmp8[t * 2 + 0]) - 1.f;
        g_vs[ng * 8 + t * 2 + 1] = 2.f * ((float)sy + tmp8[t * 2 + 1]) - 1.f;
    }
}

// ---------------- K4: bilinear KV gather + K/V proj (R4 form: one block per ng) --
// dyn smem: xp [128][65] @0 (8320) | wks [2][64][129] @8320 (16512) | kvs @24832 (512)
__global__ void __launch_bounds__(256) k_kv(
    const float* __restrict__ x, const float* __restrict__ lg,
    const float* __restrict__ lb, const float* __restrict__ wk,
    const float* __restrict__ wv) {
    extern __shared__ float sm[];
    float* xp  = sm;
    float* wks = sm + 8320;
    float* kvs = sm + 24832;
    int ng = blockIdx.x, n = ng >> 3, g = ng & 7;
    int b = n & 63, quad = n >> 6, qh = quad >> 1, qw = quad & 1;
    int t = threadIdx.x;
    #pragma unroll 8
    for (int p = 0; p < 32; p++) {
        int idx = t + (p << 8);
        int pos = idx & 63, i = idx >> 6;
        int y = (qh << 3) + (pos >> 3), xx = (qw << 3) + (pos & 7);
        int cc = (g << 7) + i;
        float raw = x[(b * 1024 + cc) * 256 + y * 16 + xx];
        int mid = (b << 8) + y * 16 + xx;
        xp[i * 65 + pos] = (raw - g_mu[mid]) * g_rstd[mid] * __ldg(lg + cc) + __ldg(lb + cc);
    }
    #pragma unroll 8
    for (int p = 0; p < 64; p++) {
        int idx = t + (p << 8);
        int which = idx >> 13, o = (idx >> 7) & 63, i = idx & 127;
        const float* wsrc = which ? wv : wk;
        wks[which * 8256 + o * 129 + i] = __ldg(wsrc + (g << 13) + (o << 7) + i);
    }
    __syncthreads();
    if (t < 128) {
        #pragma unroll
        for (int j = 0; j < 4; j++) {
            float vx = g_vs[ng * 8 + j * 2], vy = g_vs[ng * 8 + j * 2 + 1];
            float fx = ((vx + 1.f) * 8.f - 1.f) * 0.5f;
            float fy = ((vy + 1.f) * 8.f - 1.f) * 0.5f;
            float x0 = floorf(fx), y0 = floorf(fy);
            float wx1 = fx - x0, wy1 = fy - y0;
            float acc = 0.f;
            #pragma unroll
            for (int dy = 0; dy < 2; dy++)
            #pragma unroll
            for (int dx = 0; dx < 2; dx++) {
                float X = x0 + dx, Y = y0 + dy;
                if (X >= 0.f && X <= 7.f && Y >= 0.f && Y <= 7.f) {
                    float wgt = (dx ? wx1 : 1.f - wx1) * (dy ? wy1 : 1.f - wy1);
                    acc += wgt * xp[t * 65 + (int)Y * 8 + (int)X];
                }
            }
            kvs[t * 4 + j] = acc;
        }
    }
    __syncthreads();
    int o = t & 63, jp = (t >> 6) & 1, which = t >> 7;
    const float* wrow = wks + which * 8256 + o * 129;
    float a0 = 0.f, a1 = 0.f;
    #pragma unroll 4
    for (int i = 0; i < 128; i++) {
        float wt = wrow[i];
        a0 += wt * kvs[i * 4 + jp];
        a1 += wt * kvs[i * 4 + jp + 2];
    }
    float* dst = (which ? g_v : g_k) + (ng << 8);
    dst[jp * 64 + o] = a0;
    dst[(jp + 2) * 64 + o] = a1;
}

// ---------------- K5: CPB MLP (R10 config: 4wm x 2wn, mh loop, 2 blocks/SM) -----
__global__ void __launch_bounds__(256, 2) k_cpb(
    const float* __restrict__ w1, const float* __restrict__ b1,
    const float* __restrict__ b2, const float* __restrict__ w3,
    const float* __restrict__ b3) {
    extern __shared__ float sm[];
    unsigned* H1p = (unsigned*)sm;
    float* w1s = sm + 17408;
    float* bx  = sm + 18176;
    float* by  = sm + 18432;
    float* part = sm + 18688;
    int ng = blockIdx.x, t = threadIdx.x;
    int lane = t & 31, w = t >> 5, gid = lane >> 2, tig = lane & 3;
    {
        w1s[t] = w1[t]; w1s[256 + t] = w1[256 + t]; w1s[512 + t] = b1[t];
        int qi = t >> 2, j = t & 3;
        float gqx = (2.f / 7.f) * (float)(qi & 7) - 1.f;
        float gqy = (2.f / 7.f) * (float)(qi >> 3) - 1.f;
        float px = gqx - g_vs[ng * 8 + j * 2], py = gqy - g_vs[ng * 8 + j * 2 + 1];
        bx[t] = copysignf(log1pf(fabsf(px)), px);
        by[t] = copysignf(log1pf(fabsf(py)), py);
    }
    int wm = w >> 1, wn = w & 1;
    float b3v = __ldg(b3);
    const uint4* wf = (const uint4*)g_w2bf;
    __syncthreads();
    for (int np = 0; np < 2; np++) {
        {
            int col = t & 127, pr0 = (t >> 7) << 6;
            float bxv = bx[np * 128 + col], byv = by[np * 128 + col];
            #pragma unroll 4
            for (int r = 0; r < 64; r++) {
                int pr = pr0 + r;
                float h0 = fmaxf(w1s[2 * pr] * bxv + w1s[256 + 2 * pr] * byv + w1s[512 + 2 * pr], 0.f);
                float h1 = fmaxf(w1s[2 * pr + 1] * bxv + w1s[256 + 2 * pr + 1] * byv + w1s[512 + 2 * pr + 1], 0.f);
                H1p[pr * 136 + col] = pack_bf2(h0, h1);
            }
        }
        __syncthreads();
        float colsum[16];
        #pragma unroll
        for (int i2 = 0; i2 < 16; i2++) colsum[i2] = 0.f;
        #pragma unroll
        for (int mh = 0; mh < 2; mh++) {
            int mb32 = wm * 2 + mh;
            int m0 = mb32 << 5;
            float c[2][8][4];
            #pragma unroll
            for (int mt = 0; mt < 2; mt++) {
                float ba = __ldg(b2 + m0 + mt * 16 + gid);
                float bb = __ldg(b2 + m0 + mt * 16 + gid + 8);
                #pragma unroll
                for (int nt = 0; nt < 8; nt++) {
                    c[mt][nt][0] = ba; c[mt][nt][1] = ba;
                    c[mt][nt][2] = bb; c[mt][nt][3] = bb;
                }
            }
            int fbase = (mb32 * 512 + lane) * 2;
            uint4 f0 = wf[fbase], f1 = wf[fbase + 1];
            for (int kc = 0; kc < 16; kc++) {
                uint4 n0, n1;
                if (kc < 15) { n0 = wf[fbase + (kc + 1) * 64]; n1 = wf[fbase + (kc + 1) * 64 + 1]; }
                unsigned a0[4] = {f0.x, f0.y, f0.z, f0.w};
                unsigned a1[4] = {f1.x, f1.y, f1.z, f1.w};
                int rb0 = (kc * 8 + tig) * 136 + (wn << 6) + gid;
                int rb1 = rb0 + 4 * 136;
                #pragma unroll
                for (int nt = 0; nt < 8; nt++) {
                    unsigned b0 = H1p[rb0 + nt * 8];
                    unsigned bv = H1p[rb1 + nt * 8];
                    mma16(c[0][nt], a0, b0, bv);
                    mma16(c[1][nt], a1, b0, bv);
                }
                if (kc < 15) { f0 = n0; f1 = n1; }
            }
            float w3r0 = __ldg(w3 + m0 + gid),      w3r1 = __ldg(w3 + m0 + gid + 8);
            float w3r2 = __ldg(w3 + m0 + 16 + gid), w3r3 = __ldg(w3 + m0 + 24 + gid);
            #pragma unroll
            for (int nt = 0; nt < 8; nt++)
                #pragma unroll
                for (int q = 0; q < 2; q++)
                    colsum[nt * 2 + q] +=
                        w3r0 * fmaxf(c[0][nt][q], 0.f) + w3r1 * fmaxf(c[0][nt][2 + q], 0.f) +
                        w3r2 * fmaxf(c[1][nt][q], 0.f) + w3r3 * fmaxf(c[1][nt][2 + q], 0.f);
        }
        #pragma unroll
        for (int off = 4; off < 32; off <<= 1)
            #pragma unroll
            for (int i2 = 0; i2 < 16; i2++)
                colsum[i2] += __shfl_xor_sync(0xffffffffu, colsum[i2], off);
        if (gid == 0) {
            #pragma unroll
            for (int i2 = 0; i2 < 16; i2++)
                part[wm * 128 + (wn << 6) + (i2 >> 1) * 8 + tig * 2 + (i2 & 1)] = colsum[i2];
        }
        __syncthreads();
        if (t < 128) {
            float s = part[t] + part[128 + t] + part[256 + t] + part[384 + t];
            g_bias[ng * 256 + np * 128 + t] = s + b3v;
        }
        __syncthreads();
    }
}

// ---------------- K6: attention ----------------
__global__ void __launch_bounds__(256) k_att() {
    __shared__ float qs[64][65];
    __shared__ float ks4[4][65], vs4[4][65];
    __shared__ float att_s[64][5];
    int ng = blockIdx.x, n = ng >> 3, g = ng & 7;
    int t = threadIdx.x;
    #pragma unroll
    for (int p = 0; p < 16; p++) {
        int idx = t + (p << 8);
        qs[idx >> 6][idx & 63] = g_q[ng * 4096 + idx];
    }
    { int j = t >> 6, o = t & 63; ks4[j][o] = g_k[(ng << 8) + t]; vs4[j][o] = g_v[(ng << 8) + t]; }
    __syncthreads();
    int qi = t >> 2, j = t & 3;
    float s = 0.f;
    #pragma unroll 8
    for (int d = 0; d < 64; d++) s += qs[d][qi] * ks4[j][d];
    s = s * 0.125f + g_bias[(ng << 8) + t];
    float mx = fmaxf(s, __shfl_xor_sync(0xffffffffu, s, 1));
    mx = fmaxf(mx, __shfl_xor_sync(0xffffffffu, mx, 2));
    float e = __expf(s - mx);
    float sum = e;
    sum += __shfl_xor_sync(0xffffffffu, sum, 1);
    sum += __shfl_xor_sync(0xffffffffu, sum, 2);
    att_s[qi][j] = e / sum;
    __syncthreads();
    int qi2 = t & 63, dg = t >> 6;
    float a0 = att_s[qi2][0], a1 = att_s[qi2][1], a2 = att_s[qi2][2], a3 = att_s[qi2][3];
    #pragma unroll
    for (int dd = 0; dd < 16; dd++) {
        int d = (dg << 4) + dd;
        float r = a0 * vs4[0][d] + a1 * vs4[1][d] + a2 * vs4[2][d] + a3 * vs4[3][d];
        g_att[((g << 6) + d) * 16384 + (n << 6) + qi2] = r;
    }
}

// ---------------- K7: output projection, bf16 2-term split, pipelined ----------------
__global__ void __launch_bounds__(256) k_out(
    const float* __restrict__ ow, const float* __restrict__ ob,
    float* __restrict__ out) {
    __shared__ unsigned Ah[8 * 136], Am[8 * 136], Bh2[8 * 136], Bm2[8 * 136];
    int blk = blockIdx.x;
    int mb = (blk & 7) << 7, nb = (blk >> 3) << 7;
    int t = threadIdx.x, lane = t & 31, w = t >> 5;
    int gid = lane >> 2, tig = lane & 3;
    int mw = (w >> 2) << 6, nw = (w & 3) << 5;
    float c[4][4][4];
    #pragma unroll
    for (int mt = 0; mt < 4; mt++)
        #pragma unroll
        for (int nt = 0; nt < 4; nt++)
            #pragma unroll
            for (int q = 0; q < 4; q++) c[mt][nt][q] = 0.f;
    int ar = t >> 1, akq = (t & 1) << 3;
    int brp = t >> 5, bcq = (t & 31) << 2;
    float4 a0 = *(const float4*)(ow + (mb + ar) * 512 + akq);
    float4 a1 = *(const float4*)(ow + (mb + ar) * 512 + akq + 4);
    float4 bb0 = *(const float4*)(g_att + (2 * brp) * 16384 + nb + bcq);
    float4 bb1 = *(const float4*)(g_att + (2 * brp + 1) * 16384 + nb + bcq);
    for (int ck = 0; ck < 32; ck++) {
        __syncthreads();
        {
            float av[8] = {a0.x, a0.y, a0.z, a0.w, a1.x, a1.y, a1.z, a1.w};
            #pragma unroll
            for (int jj = 0; jj < 4; jj++) {
                unsigned short h0, m0v, h1, m1v;
                split_bf(av[jj * 2], h0, m0v);
                split_bf(av[jj * 2 + 1], h1, m1v);
                int p = (akq >> 1) + jj;
                Ah[p * 136 + ar] = (unsigned)h0 | ((unsigned)h1 << 16);
                Am[p * 136 + ar] = (unsigned)m0v | ((unsigned)m1v << 16);
            }
            float bv0[4] = {bb0.x, bb0.y, bb0.z, bb0.w};
            float bv1[4] = {bb1.x, bb1.y, bb1.z, bb1.w};
            #pragma unroll
            for (int jj = 0; jj < 4; jj++) {
                unsigned short h0, m0v, h1, m1v;
                split_bf(bv0[jj], h0, m0v);
                split_bf(bv1[jj], h1, m1v);
                Bh2[brp * 136 + bcq + jj] = (unsigned)h0 | ((unsigned)h1 << 16);
                Bm2[brp * 136 + bcq + jj] = (unsigned)m0v | ((unsigned)m1v << 16);
            }
        }
        __syncthreads();
        if (ck < 31) {
            int k0 = (ck + 1) << 4;
            a0 = *(const float4*)(ow + (mb + ar) * 512 + k0 + akq);
            a1 = *(const float4*)(ow + (mb + ar) * 512 + k0 + akq + 4);
            bb0 = *(const float4*)(g_att + (k0 + 2 * brp) * 16384 + nb + bcq);
            bb1 = *(const float4*)(g_att + (k0 + 2 * brp + 1) * 16384 + nb + bcq);
        }
        unsigned ah[4][4], am[4][4];
        #pragma unroll
        for (int mt = 0; mt < 4; mt++) {
            int m = mw + mt * 16 + gid;
            ah[mt][0] = Ah[tig * 136 + m];       am[mt][0] = Am[tig * 136 + m];
            ah[mt][1] = Ah[tig * 136 + m + 8];   am[mt][1] = Am[tig * 136 + m + 8];
            ah[mt][2] = Ah[(tig + 4) * 136 + m]; am[mt][2] = Am[(tig + 4) * 136 + m];
            ah[mt][3] = Ah[(tig + 4) * 136 + m + 8]; am[mt][3] = Am[(tig + 4) * 136 + m + 8];
        }
        #pragma unroll
        for (int nt = 0; nt < 4; nt++) {
            int col = nw + nt * 8 + gid;
            unsigned bh0 = Bh2[tig * 136 + col], bh1 = Bh2[(tig + 4) * 136 + col];
            unsigned bm0 = Bm2[tig * 136 + col], bm1 = Bm2[(tig + 4) * 136 + col];
            #pragma unroll
            for (int mt = 0; mt < 4; mt++) {
                mma16(c[mt][nt], ah[mt], bh0, bh1);
                mma16(c[mt][nt], am[mt], bh0, bh1);
                mma16(c[mt][nt], ah[mt], bm0, bm1);
            }
        }
    }
    #pragma unroll
    for (int mt = 0; mt < 4; mt++)
        #pragma unroll
        for (int nt = 0; nt < 4; nt++)
            #pragma unroll
            for (int q = 0; q < 4; q++) {
                int o = mb + mw + mt * 16 + gid + ((q >> 1) << 3);
                int col = nb + nw + nt * 8 + tig * 2 + (q & 1);
                int n = col >> 6, qi = col & 63;
                int b = n & 63, quad = n >> 6;
                int y = ((quad >> 1) << 3) + (qi >> 3);
                int xx = ((quad & 1) << 3) + (qi & 7);
                out[((b * 1024 + o) * 16 + y) * 16 + xx] = c[mt][nt][q] + __ldg(ob + o);
            }
}

extern "C" void kernel_launch(void* const* d_in, const int* in_sizes, int n_in,
                              void* d_out, int out_size) {
    const float* x      = (const float*)d_in[0];
    const float* ln_g   = (const float*)d_in[1];
    const float* ln_b   = (const float*)d_in[2];
    const float* wq     = (const float*)d_in[3];
    const float* wk     = (const float*)d_in[4];
    const float* wv     = (const float*)d_in[5];
    const float* off_w1 = (const float*)d_in[6];
    const float* off_b1 = (const float*)d_in[7];
    const float* off_w2 = (const float*)d_in[8];
    const float* cpb_w1 = (const float*)d_in[9];
    const float* cpb_b1 = (const float*)d_in[10];
    const float* cpb_w2 = (const float*)d_in[11];
    const float* cpb_b2 = (const float*)d_in[12];
    const float* cpb_w3 = (const float*)d_in[13];
    const float* cpb_b3 = (const float*)d_in[14];
    const float* out_w  = (const float*)d_in[15];
    const float* out_b  = (const float*)d_in[16];
    float* out = (float*)d_out;
    const int KV_SMEM  = 25344 * 4;   // 101376 B
    const int CPB_SMEM = 19200 * 4;   // 76800 B (2 blocks/SM)
    cudaFuncSetAttribute(k_kv,  cudaFuncAttributeMaxDynamicSharedMemorySize, KV_SMEM);
    cudaFuncSetAttribute(k_cpb, cudaFuncAttributeMaxDynamicSharedMemorySize, CPB_SMEM);
    k_ln<<<512, 256>>>(x, cpb_w2, wq);
    k_qproj<<<2048, 256>>>(x, ln_g, ln_b, off_w1, off_b1, off_w2);
    k_cpb<<<2048, 256, CPB_SMEM>>>(cpb_w1, cpb_b1, cpb_b2, cpb_w3, cpb_b3);
    k_kv<<<2048, 256, KV_SMEM>>>(x, ln_g, ln_b, wk, wv);
    k_att<<<2048, 256>>>();
    k_out<<<1024, 256>>>(out_w, out_b, out);
}

// round 15
// speedup vs baseline: 1.1894x; 1.0765x over previous
#include <cuda_runtime.h>
#include <cuda_bf16.h>
#include <math.h>

#define DEVI __device__ __forceinline__

__device__ float g_mu[16384];
__device__ float g_rstd[16384];
__device__ float g_q[2048 * 4096];     // [ng][o][pos]
__device__ float g_vs[2048 * 8];       // [ng][j][x,y]
__device__ float g_k[2048 * 256];      // [ng][j][o]
__device__ float g_v[2048 * 256];
__device__ float g_bias[2048 * 256];   // [ng][qi*4+j]
__device__ float g_att[512 * 16384];   // [c][n*64+qi]
__device__ unsigned g_w2bf[32768];     // fragment-ordered bf16x2 of cpb_w2
__device__ unsigned g_wqh[32768];      // wq hi  bf16x2: [g][kp=64][m=64]
__device__ unsigned g_wqm[32768];      // wq mid bf16x2
__device__ float g_wkT[65536];         // wk transposed [g][i=128][o=64]
__device__ float g_wvT[65536];         // wv transposed

DEVI void mma16(float* c, const unsigned* a, unsigned b0, unsigned b1) {
    asm("mma.sync.aligned.m16n8k16.row.col.f32.bf16.bf16.f32 "
        "{%0,%1,%2,%3}, {%4,%5,%6,%7}, {%8,%9}, {%0,%1,%2,%3};"
        : "+f"(c[0]), "+f"(c[1]), "+f"(c[2]), "+f"(c[3])
        : "r"(a[0]), "r"(a[1]), "r"(a[2]), "r"(a[3]), "r"(b0), "r"(b1));
}
DEVI unsigned pack_bf2(float lo, float hi) {
    unsigned a = (unsigned)__bfloat16_as_ushort(__float2bfloat16_rn(lo));
    unsigned b = (unsigned)__bfloat16_as_ushort(__float2bfloat16_rn(hi));
    return a | (b << 16);
}
DEVI void split_bf(float v, unsigned short& h, unsigned short& m) {
    __nv_bfloat16 bh = __float2bfloat16_rn(v);
    float hv = __bfloat162float(bh);
    h = __bfloat16_as_ushort(bh);
    m = __bfloat16_as_ushort(__float2bfloat16_rn(v - hv));
}

// ---------------- K1: LayerNorm stats + weight packing/transposes ----------------
__global__ void __launch_bounds__(256) k_ln(const float* __restrict__ x,
                                           const float* __restrict__ w2,
                                           const float* __restrict__ wq,
                                           const float* __restrict__ wk,
                                           const float* __restrict__ wv) {
    int fi = blockIdx.x * 256 + threadIdx.x;
    if (fi < 32768) {
        int u = fi & 7, lane = (fi >> 3) & 31, kc = (fi >> 8) & 15, mb32 = fi >> 12;
        int tig = lane & 3, gid = lane >> 2;
        int mt = u >> 2, q = u & 3;
        int k2 = kc * 8 + tig + ((q & 2) ? 4 : 0);
        int m = mb32 * 32 + mt * 16 + gid + ((q & 1) ? 8 : 0);
        g_w2bf[fi] = pack_bf2(w2[(2 * k2) * 256 + m], w2[(2 * k2 + 1) * 256 + m]);
        int g = fi >> 12, kp = (fi >> 6) & 63, m2 = fi & 63;
        float v0 = wq[g * 8192 + m2 * 128 + 2 * kp];
        float v1 = wq[g * 8192 + m2 * 128 + 2 * kp + 1];
        unsigned short h0, mm0, h1, mm1;
        split_bf(v0, h0, mm0);
        split_bf(v1, h1, mm1);
        g_wqh[fi] = (unsigned)h0 | ((unsigned)h1 << 16);
        g_wqm[fi] = (unsigned)mm0 | ((unsigned)mm1 << 16);
    }
    if (fi < 65536) {
        int g = fi >> 13, i = (fi >> 6) & 127, o = fi & 63;
        g_wkT[fi] = wk[g * 8192 + o * 128 + i];
        g_wvT[fi] = wv[g * 8192 + o * 128 + i];
    }
    int b = blockIdx.x >> 3, rp = blockIdx.x & 7;
    int t = threadIdx.x, pl = t & 31, w = t >> 5;
    const float* px = x + b * 262144 + rp * 32 + pl;
    float s = 0.f, q2 = 0.f;
    for (int c = w; c < 1024; c += 8) { float v = px[c * 256]; s += v; q2 += v * v; }
    __shared__ float rs[8][32], rq[8][32];
    rs[w][pl] = s; rq[w][pl] = q2;
    __syncthreads();
    if (t < 32) {
        float S = 0.f, Q = 0.f;
        #pragma unroll
        for (int i = 0; i < 8; i++) { S += rs[i][t]; Q += rq[i][t]; }
        float mu = S * (1.f / 1024.f);
        float var = Q * (1.f / 1024.f) - mu * mu;
        g_mu[b * 256 + rp * 32 + t] = mu;
        g_rstd[b * 256 + rp * 32 + t] = rsqrtf(var + 1e-6f);
    }
}

// ---------------- K2: Q projection (bf16 3-mma) + fused offset head ----------------
__global__ void __launch_bounds__(256) k_qproj(
    const float* __restrict__ x, const float* __restrict__ lg,
    const float* __restrict__ lb, const float* __restrict__ ow1,
    const float* __restrict__ ob1, const float* __restrict__ ow2) {
    __shared__ unsigned Xh[64 * 72], Xm[64 * 72];
    __shared__ float tmp8[8];
    int ng = blockIdx.x, n = ng >> 3, g = ng & 7;
    int b = n & 63, quad = n >> 6, qh = quad >> 1, qw = quad & 1;
    int t = threadIdx.x;
    #pragma unroll 4
    for (int pass = 0; pass < 16; pass++) {
        int e = t + (pass << 8);
        int pos = e & 63, kp = e >> 6;
        int y = (qh << 3) + (pos >> 3), xx = (qw << 3) + (pos & 7);
        int cc0 = (g << 7) + 2 * kp;
        int mid = (b << 8) + y * 16 + xx;
        float mu = g_mu[mid], rstd = g_rstd[mid];
        float x0 = x[(b * 1024 + cc0) * 256 + y * 16 + xx];
        float x1 = x[(b * 1024 + cc0 + 1) * 256 + y * 16 + xx];
        float v0 = (x0 - mu) * rstd * __ldg(lg + cc0) + __ldg(lb + cc0);
        float v1 = (x1 - mu) * rstd * __ldg(lg + cc0 + 1) + __ldg(lb + cc0 + 1);
        unsigned short h0, m0v, h1, m1v;
        split_bf(v0, h0, m0v);
        split_bf(v1, h1, m1v);
        Xh[kp * 72 + pos] = (unsigned)h0 | ((unsigned)h1 << 16);
        Xm[kp * 72 + pos] = (unsigned)m0v | ((unsigned)m1v << 16);
    }
    __syncthreads();
    int lane = t & 31, w = t >> 5, gid = lane >> 2, tig = lane & 3;
    int wm = w >> 1, wn = w & 1;
    int m = wm * 16 + gid;
    const unsigned* qhp = g_wqh + (g << 12);
    const unsigned* qmp = g_wqm + (g << 12);
    float c[4][4];
    #pragma unroll
    for (int nt = 0; nt < 4; nt++) { c[nt][0] = 0.f; c[nt][1] = 0.f; c[nt][2] = 0.f; c[nt][3] = 0.f; }
    #pragma unroll
    for (int ks = 0; ks < 8; ks++) {
        int kp0 = ks * 8 + tig;
        unsigned ah[4], am[4];
        ah[0] = qhp[kp0 * 64 + m];       ah[1] = qhp[kp0 * 64 + m + 8];
        ah[2] = qhp[(kp0 + 4) * 64 + m]; ah[3] = qhp[(kp0 + 4) * 64 + m + 8];
        am[0] = qmp[kp0 * 64 + m];       am[1] = qmp[kp0 * 64 + m + 8];
        am[2] = qmp[(kp0 + 4) * 64 + m]; am[3] = qmp[(kp0 + 4) * 64 + m + 8];
        #pragma unroll
        for (int nt = 0; nt < 4; nt++) {
            int col = wn * 32 + nt * 8 + gid;
            unsigned bh0 = Xh[kp0 * 72 + col], bh1 = Xh[(kp0 + 4) * 72 + col];
            unsigned bm0 = Xm[kp0 * 72 + col], bm1 = Xm[(kp0 + 4) * 72 + col];
            mma16(c[nt], ah, bh0, bh1);
            mma16(c[nt], am, bh0, bh1);
            mma16(c[nt], ah, bm0, bm1);
        }
    }
    __syncthreads();
    float* qf = (float*)Xh;
    float* cb = (float*)Xm;
    float* qo = g_q + ng * 4096;
    #pragma unroll
    for (int nt = 0; nt < 4; nt++)
        #pragma unroll
        for (int q = 0; q < 4; q++) {
            int o = wm * 16 + gid + ((q >> 1) << 3);
            int pos = wn * 32 + nt * 8 + tig * 2 + (q & 1);
            qo[o * 64 + pos] = c[nt][q];
            qf[o * 65 + pos] = c[nt][q];
        }
    __syncthreads();
    if (t < 64) {
        float wr[36];
        #pragma unroll
        for (int u = 0; u < 36; u++) wr[u] = ow1[t * 36 + u];
        float bias = ob1[t], w2a = ow2[t], w2b = ow2[64 + t];
        #pragma unroll
        for (int sy = 0; sy < 2; sy++)
        #pragma unroll
        for (int sx = 0; sx < 2; sx++) {
            float s = bias;
            #pragma unroll
            for (int ky = 0; ky < 6; ky++) {
                int iy = sy * 4 - 1 + ky;
                if (iy < 0 || iy > 7) continue;
                #pragma unroll
                for (int kx = 0; kx < 6; kx++) {
                    int ix = sx * 4 - 1 + kx;
                    if (ix < 0 || ix > 7) continue;
                    s += wr[ky * 6 + kx] * qf[t * 65 + iy * 8 + ix];
                }
            }
            float gl = 0.5f * s * (1.f + erff(s * 0.70710678118654752f));
            cb[t * 8 + (sy * 2 + sx) * 2 + 0] = gl * w2a;
            cb[t * 8 + (sy * 2 + sx) * 2 + 1] = gl * w2b;
        }
    }
    __syncthreads();
    if (t < 8) {
        float s = 0.f;
        for (int cc = 0; cc < 64; cc++) s += cb[cc * 8 + t];
        tmp8[t] = 4.f * tanhf(s);
    }
    __syncthreads();
    if (t < 4) {
        int sy = t >> 1, sx = t & 1;
        g_vs[ng * 8 + t * 2 + 0] = 2.f * ((float)sx + tmp8[t * 2 + 0]) - 1.f;
        g_vs[ng * 8 + t * 2 + 1] = 2.f * ((float)sy + tmp8[t * 2 + 1]) - 1.f;
    }
}

// ---------------- K4: bilinear KV gather + proj (transposed weights, 35KB smem) --
__global__ void __launch_bounds__(256) k_kv(
    const float* __restrict__ x, const float* __restrict__ lg,
    const float* __restrict__ lb) {
    extern __shared__ float sm[];
    float* xp  = sm;
    float* kvs = sm + 8320;
    int ng = blockIdx.x, n = ng >> 3, g = ng & 7;
    int b = n & 63, quad = n >> 6, qh = quad >> 1, qw = quad & 1;
    int t = threadIdx.x;
    #pragma unroll 8
    for (int p = 0; p < 32; p++) {
        int idx = t + (p << 8);
        int pos = idx & 63, i = idx >> 6;
        int y = (qh << 3) + (pos >> 3), xx = (qw << 3) + (pos & 7);
        int cc = (g << 7) + i;
        float raw = x[(b * 1024 + cc) * 256 + y * 16 + xx];
        int mid = (b << 8) + y * 16 + xx;
        xp[i * 65 + pos] = (raw - g_mu[mid]) * g_rstd[mid] * __ldg(lg + cc) + __ldg(lb + cc);
    }
    __syncthreads();
    if (t < 128) {
        #pragma unroll
        for (int j = 0; j < 4; j++) {
            float vx = g_vs[ng * 8 + j * 2], vy = g_vs[ng * 8 + j * 2 + 1];
            float fx = ((vx + 1.f) * 8.f - 1.f) * 0.5f;
            float fy = ((vy + 1.f) * 8.f - 1.f) * 0.5f;
            float x0 = floorf(fx), y0 = floorf(fy);
            float wx1 = fx - x0, wy1 = fy - y0;
            float acc = 0.f;
            #pragma unroll
            for (int dy = 0; dy < 2; dy++)
            #pragma unroll
            for (int dx = 0; dx < 2; dx++) {
                float X = x0 + dx, Y = y0 + dy;
                if (X >= 0.f && X <= 7.f && Y >= 0.f && Y <= 7.f) {
                    float wgt = (dx ? wx1 : 1.f - wx1) * (dy ? wy1 : 1.f - wy1);
                    acc += wgt * xp[t * 65 + (int)Y * 8 + (int)X];
                }
            }
            kvs[t * 4 + j] = acc;
        }
    }
    __syncthreads();
    int o = t & 63, jp = (t >> 6) & 1, which = t >> 7;
    const float* wT = (which ? g_wvT : g_wkT) + (g << 13) + o;
    float a0 = 0.f, a1 = 0.f;
    #pragma unroll 8
    for (int i = 0; i < 128; i++) {
        float wt = __ldg(wT + i * 64);
        a0 += wt * kvs[i * 4 + jp];
        a1 += wt * kvs[i * 4 + jp + 2];
    }
    float* dst = (which ? g_v : g_k) + (ng << 8);
    dst[jp * 64 + o] = a0;
    dst[(jp + 2) * 64 + o] = a1;
}

// ---------------- K5: CPB MLP (R10 config: 4wm x 2wn, mh loop, 2 blocks/SM) -----
__global__ void __launch_bounds__(256, 2) k_cpb(
    const float* __restrict__ w1, const float* __restrict__ b1,
    const float* __restrict__ b2, const float* __restrict__ w3,
    const float* __restrict__ b3) {
    extern __shared__ float sm[];
    unsigned* H1p = (unsigned*)sm;
    float* w1s = sm + 17408;
    float* bx  = sm + 18176;
    float* by  = sm + 18432;
    float* part = sm + 18688;
    int ng = blockIdx.x, t = threadIdx.x;
    int lane = t & 31, w = t >> 5, gid = lane >> 2, tig = lane & 3;
    {
        w1s[t] = w1[t]; w1s[256 + t] = w1[256 + t]; w1s[512 + t] = b1[t];
        int qi = t >> 2, j = t & 3;
        float gqx = (2.f / 7.f) * (float)(qi & 7) - 1.f;
        float gqy = (2.f / 7.f) * (float)(qi >> 3) - 1.f;
        float px = gqx - g_vs[ng * 8 + j * 2], py = gqy - g_vs[ng * 8 + j * 2 + 1];
        bx[t] = copysignf(log1pf(fabsf(px)), px);
        by[t] = copysignf(log1pf(fabsf(py)), py);
    }
    int wm = w >> 1, wn = w & 1;
    float b3v = __ldg(b3);
    const uint4* wf = (const uint4*)g_w2bf;
    __syncthreads();
    for (int np = 0; np < 2; np++) {
        {
            int col = t & 127, pr0 = (t >> 7) << 6;
            float bxv = bx[np * 128 + col], byv = by[np * 128 + col];
            #pragma unroll 4
            for (int r = 0; r < 64; r++) {
                int pr = pr0 + r;
                float h0 = fmaxf(w1s[2 * pr] * bxv + w1s[256 + 2 * pr] * byv + w1s[512 + 2 * pr], 0.f);
                float h1 = fmaxf(w1s[2 * pr + 1] * bxv + w1s[256 + 2 * pr + 1] * byv + w1s[512 + 2 * pr + 1], 0.f);
                H1p[pr * 136 + col] = pack_bf2(h0, h1);
            }
        }
        __syncthreads();
        float colsum[16];
        #pragma unroll
        for (int i2 = 0; i2 < 16; i2++) colsum[i2] = 0.f;
        #pragma unroll
        for (int mh = 0; mh < 2; mh++) {
            int mb32 = wm * 2 + mh;
            int m0 = mb32 << 5;
            float c[2][8][4];
            #pragma unroll
            for (int mt = 0; mt < 2; mt++) {
                float ba = __ldg(b2 + m0 + mt * 16 + gid);
                float bb = __ldg(b2 + m0 + mt * 16 + gid + 8);
                #pragma unroll
                for (int nt = 0; nt < 8; nt++) {
                    c[mt][nt][0] = ba; c[mt][nt][1] = ba;
                    c[mt][nt][2] = bb; c[mt][nt][3] = bb;
                }
            }
            int fbase = (mb32 * 512 + lane) * 2;
            uint4 f0 = wf[fbase], f1 = wf[fbase + 1];
            for (int kc = 0; kc < 16; kc++) {
                uint4 n0, n1;
                if (kc < 15) { n0 = wf[fbase + (kc + 1) * 64]; n1 = wf[fbase + (kc + 1) * 64 + 1]; }
                unsigned a0[4] = {f0.x, f0.y, f0.z, f0.w};
                unsigned a1[4] = {f1.x, f1.y, f1.z, f1.w};
                int rb0 = (kc * 8 + tig) * 136 + (wn << 6) + gid;
                int rb1 = rb0 + 4 * 136;
                #pragma unroll
                for (int nt = 0; nt < 8; nt++) {
                    unsigned b0 = H1p[rb0 + nt * 8];
                    unsigned bv = H1p[rb1 + nt * 8];
                    mma16(c[0][nt], a0, b0, bv);
                    mma16(c[1][nt], a1, b0, bv);
                }
                if (kc < 15) { f0 = n0; f1 = n1; }
            }
            float w3r0 = __ldg(w3 + m0 + gid),      w3r1 = __ldg(w3 + m0 + gid + 8);
            float w3r2 = __ldg(w3 + m0 + 16 + gid), w3r3 = __ldg(w3 + m0 + 24 + gid);
            #pragma unroll
            for (int nt = 0; nt < 8; nt++)
                #pragma unroll
                for (int q = 0; q < 2; q++)
                    colsum[nt * 2 + q] +=
                        w3r0 * fmaxf(c[0][nt][q], 0.f) + w3r1 * fmaxf(c[0][nt][2 + q], 0.f) +
                        w3r2 * fmaxf(c[1][nt][q], 0.f) + w3r3 * fmaxf(c[1][nt][2 + q], 0.f);
        }
        #pragma unroll
        for (int off = 4; off < 32; off <<= 1)
            #pragma unroll
            for (int i2 = 0; i2 < 16; i2++)
                colsum[i2] += __shfl_xor_sync(0xffffffffu, colsum[i2], off);
        if (gid == 0) {
            #pragma unroll
            for (int i2 = 0; i2 < 16; i2++)
                part[wm * 128 + (wn << 6) + (i2 >> 1) * 8 + tig * 2 + (i2 & 1)] = colsum[i2];
        }
        __syncthreads();
        if (t < 128) {
            float s = part[t] + part[128 + t] + part[256 + t] + part[384 + t];
            g_bias[ng * 256 + np * 128 + t] = s + b3v;
        }
        __syncthreads();
    }
}

// ---------------- K6: attention ----------------
__global__ void __launch_bounds__(256) k_att() {
    __shared__ float qs[64][65];
    __shared__ float ks4[4][65], vs4[4][65];
    __shared__ float att_s[64][5];
    int ng = blockIdx.x, n = ng >> 3, g = ng & 7;
    int t = threadIdx.x;
    #pragma unroll
    for (int p = 0; p < 16; p++) {
        int idx = t + (p << 8);
        qs[idx >> 6][idx & 63] = g_q[ng * 4096 + idx];
    }
    { int j = t >> 6, o = t & 63; ks4[j][o] = g_k[(ng << 8) + t]; vs4[j][o] = g_v[(ng << 8) + t]; }
    __syncthreads();
    int qi = t >> 2, j = t & 3;
    float s = 0.f;
    #pragma unroll 8
    for (int d = 0; d < 64; d++) s += qs[d][qi] * ks4[j][d];
    s = s * 0.125f + g_bias[(ng << 8) + t];
    float mx = fmaxf(s, __shfl_xor_sync(0xffffffffu, s, 1));
    mx = fmaxf(mx, __shfl_xor_sync(0xffffffffu, mx, 2));
    float e = __expf(s - mx);
    float sum = e;
    sum += __shfl_xor_sync(0xffffffffu, sum, 1);
    sum += __shfl_xor_sync(0xffffffffu, sum, 2);
    att_s[qi][j] = e / sum;
    __syncthreads();
    int qi2 = t & 63, dg = t >> 6;
    float a0 = att_s[qi2][0], a1 = att_s[qi2][1], a2 = att_s[qi2][2], a3 = att_s[qi2][3];
    #pragma unroll
    for (int dd = 0; dd < 16; dd++) {
        int d = (dg << 4) + dd;
        float r = a0 * vs4[0][d] + a1 * vs4[1][d] + a2 * vs4[2][d] + a3 * vs4[3][d];
        g_att[((g << 6) + d) * 16384 + (n << 6) + qi2] = r;
    }
}

// ---------------- K7: output projection, bf16 2-term split, pipelined ----------------
__global__ void __launch_bounds__(256) k_out(
    const float* __restrict__ ow, const float* __restrict__ ob,
    float* __restrict__ out) {
    __shared__ unsigned Ah[8 * 136], Am[8 * 136], Bh2[8 * 136], Bm2[8 * 136];
    int blk = blockIdx.x;
    int mb = (blk & 7) << 7, nb = (blk >> 3) << 7;
    int t = threadIdx.x, lane = t & 31, w = t >> 5;
    int gid = lane >> 2, tig = lane & 3;
    int mw = (w >> 2) << 6, nw = (w & 3) << 5;
    float c[4][4][4];
    #pragma unroll
    for (int mt = 0; mt < 4; mt++)
        #pragma unroll
        for (int nt = 0; nt < 4; nt++)
            #pragma unroll
            for (int q = 0; q < 4; q++) c[mt][nt][q] = 0.f;
    int ar = t >> 1, akq = (t & 1) << 3;
    int brp = t >> 5, bcq = (t & 31) << 2;
    float4 a0 = *(const float4*)(ow + (mb + ar) * 512 + akq);
    float4 a1 = *(const float4*)(ow + (mb + ar) * 512 + akq + 4);
    float4 bb0 = *(const float4*)(g_att + (2 * brp) * 16384 + nb + bcq);
    float4 bb1 = *(const float4*)(g_att + (2 * brp + 1) * 16384 + nb + bcq);
    for (int ck = 0; ck < 32; ck++) {
        __syncthreads();
        {
            float av[8] = {a0.x, a0.y, a0.z, a0.w, a1.x, a1.y, a1.z, a1.w};
            #pragma unroll
            for (int jj = 0; jj < 4; jj++) {
                unsigned short h0, m0v, h1, m1v;
                split_bf(av[jj * 2], h0, m0v);
                split_bf(av[jj * 2 + 1], h1, m1v);
                int p = (akq >> 1) + jj;
                Ah[p * 136 + ar] = (unsigned)h0 | ((unsigned)h1 << 16);
                Am[p * 136 + ar] = (unsigned)m0v | ((unsigned)m1v << 16);
            }
            float bv0[4] = {bb0.x, bb0.y, bb0.z, bb0.w};
            float bv1[4] = {bb1.x, bb1.y, bb1.z, bb1.w};
            #pragma unroll
            for (int jj = 0; jj < 4; jj++) {
                unsigned short h0, m0v, h1, m1v;
                split_bf(bv0[jj], h0, m0v);
                split_bf(bv1[jj], h1, m1v);
                Bh2[brp * 136 + bcq + jj] = (unsigned)h0 | ((unsigned)h1 << 16);
                Bm2[brp * 136 + bcq + jj] = (unsigned)m0v | ((unsigned)m1v << 16);
            }
        }
        __syncthreads();
        if (ck < 31) {
            int k0 = (ck + 1) << 4;
            a0 = *(const float4*)(ow + (mb + ar) * 512 + k0 + akq);
            a1 = *(const float4*)(ow + (mb + ar) * 512 + k0 + akq + 4);
            bb0 = *(const float4*)(g_att + (k0 + 2 * brp) * 16384 + nb + bcq);
            bb1 = *(const float4*)(g_att + (k0 + 2 * brp + 1) * 16384 + nb + bcq);
        }
        unsigned ah[4][4], am[4][4];
        #pragma unroll
        for (int mt = 0; mt < 4; mt++) {
            int m = mw + mt * 16 + gid;
            ah[mt][0] = Ah[tig * 136 + m];       am[mt][0] = Am[tig * 136 + m];
            ah[mt][1] = Ah[tig * 136 + m + 8];   am[mt][1] = Am[tig * 136 + m + 8];
            ah[mt][2] = Ah[(tig + 4) * 136 + m]; am[mt][2] = Am[(tig + 4) * 136 + m];
            ah[mt][3] = Ah[(tig + 4) * 136 + m + 8]; am[mt][3] = Am[(tig + 4) * 136 + m + 8];
        }
        #pragma unroll
        for (int nt = 0; nt < 4; nt++) {
            int col = nw + nt * 8 + gid;
            unsigned bh0 = Bh2[tig * 136 + col], bh1 = Bh2[(tig + 4) * 136 + col];
            unsigned bm0 = Bm2[tig * 136 + col], bm1 = Bm2[(tig + 4) * 136 + col];
            #pragma unroll
            for (int mt = 0; mt < 4; mt++) {
                mma16(c[mt][nt], ah[mt], bh0, bh1);
                mma16(c[mt][nt], am[mt], bh0, bh1);
                mma16(c[mt][nt], ah[mt], bm0, bm1);
            }
        }
    }
    #pragma unroll
    for (int mt = 0; mt < 4; mt++)
        #pragma unroll
        for (int nt = 0; nt < 4; nt++)
            #pragma unroll
            for (int q = 0; q < 4; q++) {
                int o = mb + mw + mt * 16 + gid + ((q >> 1) << 3);
                int col = nb + nw + nt * 8 + tig * 2 + (q & 1);
                int n = col >> 6, qi = col & 63;
                int b = n & 63, quad = n >> 6;
                int y = ((quad >> 1) << 3) + (qi >> 3);
                int xx = ((quad & 1) << 3) + (qi & 7);
                out[((b * 1024 + o) * 16 + y) * 16 + xx] = c[mt][nt][q] + __ldg(ob + o);
            }
}

extern "C" void kernel_launch(void* const* d_in, const int* in_sizes, int n_in,
                              void* d_out, int out_size) {
    const float* x      = (const float*)d_in[0];
    const float* ln_g   = (const float*)d_in[1];
    const float* ln_b   = (const float*)d_in[2];
    const float* wq     = (const float*)d_in[3];
    const float* wk     = (const float*)d_in[4];
    const float* wv     = (const float*)d_in[5];
    const float* off_w1 = (const float*)d_in[6];
    const float* off_b1 = (const float*)d_in[7];
    const float* off_w2 = (const float*)d_in[8];
    const float* cpb_w1 = (const float*)d_in[9];
    const float* cpb_b1 = (const float*)d_in[10];
    const float* cpb_w2 = (const float*)d_in[11];
    const float* cpb_b2 = (const float*)d_in[12];
    const float* cpb_w3 = (const float*)d_in[13];
    const float* cpb_b3 = (const float*)d_in[14];
    const float* out_w  = (const float*)d_in[15];
    const float* out_b  = (const float*)d_in[16];
    float* out = (float*)d_out;
    const int KV_SMEM  = 8832 * 4;    // 35328 B
    const int CPB_SMEM = 19200 * 4;   // 76800 B (2 blocks/SM)
    cudaFuncSetAttribute(k_kv,  cudaFuncAttributeMaxDynamicSharedMemorySize, KV_SMEM);
    cudaFuncSetAttribute(k_cpb, cudaFuncAttributeMaxDynamicSharedMemorySize, CPB_SMEM);
    k_ln<<<512, 256>>>(x, cpb_w2, wq, wk, wv);
    k_qproj<<<2048, 256>>>(x, ln_g, ln_b, off_w1, off_b1, off_w2);
    k_cpb<<<2048, 256, CPB_SMEM>>>(cpb_w1, cpb_b1, cpb_b2, cpb_w3, cpb_b3);
    k_kv<<<2048, 256, KV_SMEM>>>(x, ln_g, ln_b);
    k_att<<<2048, 256>>>();
    k_out<<<1024, 256>>>(out_w, out_b, out);
}

// round 16
// speedup vs baseline: 1.1897x; 1.0002x over previous
#include <cuda_runtime.h>
#include <cuda_bf16.h>
#include <math.h>

#define DEVI __device__ __forceinline__

__device__ float g_mu[16384];
__device__ float g_rstd[16384];
__device__ float g_q[2048 * 4096];     // [ng][o][pos]
__device__ float g_vs[2048 * 8];       // [ng][j][x,y]
__device__ float g_k[2048 * 256];      // [ng][j][o]
__device__ float g_v[2048 * 256];
__device__ float g_bias[2048 * 256];   // [ng][qi*4+j]
__device__ unsigned g_atth[256 * 16384]; // attention out, bf16x2 hi, [kp][col]
__device__ unsigned g_attm[256 * 16384]; // bf16x2 mid
__device__ unsigned g_w2bf[32768];     // fragment-ordered bf16x2 of cpb_w2
__device__ unsigned g_wqh[32768];      // wq hi  bf16x2: [g][kp=64][m=64]
__device__ unsigned g_wqm[32768];      // wq mid bf16x2
__device__ float g_wkT[65536];         // wk transposed [g][i=128][o=64]
__device__ float g_wvT[65536];         // wv transposed
__device__ unsigned g_owfh[262144];    // out_w frag-packed hi  (16 m64g x 32 ck x 32 lane x 4 mt) uint4
__device__ unsigned g_owfm[262144];    // out_w frag-packed mid

DEVI void mma16(float* c, const unsigned* a, unsigned b0, unsigned b1) {
    asm("mma.sync.aligned.m16n8k16.row.col.f32.bf16.bf16.f32 "
        "{%0,%1,%2,%3}, {%4,%5,%6,%7}, {%8,%9}, {%0,%1,%2,%3};"
        : "+f"(c[0]), "+f"(c[1]), "+f"(c[2]), "+f"(c[3])
        : "r"(a[0]), "r"(a[1]), "r"(a[2]), "r"(a[3]), "r"(b0), "r"(b1));
}
DEVI unsigned pack_bf2(float lo, float hi) {
    unsigned a = (unsigned)__bfloat16_as_ushort(__float2bfloat16_rn(lo));
    unsigned b = (unsigned)__bfloat16_as_ushort(__float2bfloat16_rn(hi));
    return a | (b << 16);
}
DEVI void split_bf(float v, unsigned short& h, unsigned short& m) {
    __nv_bfloat16 bh = __float2bfloat16_rn(v);
    float hv = __bfloat162float(bh);
    h = __bfloat16_as_ushort(bh);
    m = __bfloat16_as_ushort(__float2bfloat16_rn(v - hv));
}
DEVI unsigned split_sel(float v, int mid) {
    unsigned short h, m;
    split_bf(v, h, m);
    return mid ? (unsigned)m : (unsigned)h;
}

// ---------------- K1: LayerNorm stats + weight packing/transposes ----------------
__global__ void __launch_bounds__(256) k_ln(const float* __restrict__ x,
                                           const float* __restrict__ w2,
                                           const float* __restrict__ wq,
                                           const float* __restrict__ wk,
                                           const float* __restrict__ wv,
                                           const float* __restrict__ ow) {
    int fi = blockIdx.x * 256 + threadIdx.x;
    if (fi < 32768) {
        int u = fi & 7, lane = (fi >> 3) & 31, kc = (fi >> 8) & 15, mb32 = fi >> 12;
        int tig = lane & 3, gid = lane >> 2;
        int mt = u >> 2, q = u & 3;
        int k2 = kc * 8 + tig + ((q & 2) ? 4 : 0);
        int m = mb32 * 32 + mt * 16 + gid + ((q & 1) ? 8 : 0);
        g_w2bf[fi] = pack_bf2(w2[(2 * k2) * 256 + m], w2[(2 * k2 + 1) * 256 + m]);
        int g = fi >> 12, kp = (fi >> 6) & 63, m2 = fi & 63;
        float v0 = wq[g * 8192 + m2 * 128 + 2 * kp];
        float v1 = wq[g * 8192 + m2 * 128 + 2 * kp + 1];
        unsigned short h0, mm0, h1, mm1;
        split_bf(v0, h0, mm0);
        split_bf(v1, h1, mm1);
        g_wqh[fi] = (unsigned)h0 | ((unsigned)h1 << 16);
        g_wqm[fi] = (unsigned)mm0 | ((unsigned)mm1 << 16);
    }
    if (fi < 65536) {
        int g = fi >> 13, i = (fi >> 6) & 127, o = fi & 63;
        g_wkT[fi] = wk[g * 8192 + o * 128 + i];
        g_wvT[fi] = wv[g * 8192 + o * 128 + i];
    }
    {   // out_w fragment packing: one uint4 per thread (fi covers 131072 exactly)
        int u = fi & 7, lane = (fi >> 3) & 31, ck = (fi >> 8) & 31, m64g = fi >> 13;
        int tig = lane & 3, gid = lane >> 2;
        int mt = u & 3, ish = u >> 2;
        int kp = ck * 8 + tig;
        int m = m64g * 64 + mt * 16 + gid;
        unsigned j0 = split_sel(ow[m * 512 + 2 * kp], ish)
                    | (split_sel(ow[m * 512 + 2 * kp + 1], ish) << 16);
        unsigned j1 = split_sel(ow[(m + 8) * 512 + 2 * kp], ish)
                    | (split_sel(ow[(m + 8) * 512 + 2 * kp + 1], ish) << 16);
        unsigned j2 = split_sel(ow[m * 512 + 2 * (kp + 4)], ish)
                    | (split_sel(ow[m * 512 + 2 * (kp + 4) + 1], ish) << 16);
        unsigned j3 = split_sel(ow[(m + 8) * 512 + 2 * (kp + 4)], ish)
                    | (split_sel(ow[(m + 8) * 512 + 2 * (kp + 4) + 1], ish) << 16);
        int oidx = ((m64g * 32 + ck) * 32 + lane) * 4 + mt;
        uint4 v4 = make_uint4(j0, j1, j2, j3);
        if (ish == 0) ((uint4*)g_owfh)[oidx] = v4;
        else          ((uint4*)g_owfm)[oidx] = v4;
    }
    int b = blockIdx.x >> 3, rp = blockIdx.x & 7;
    int t = threadIdx.x, pl = t & 31, w = t >> 5;
    const float* px = x + b * 262144 + rp * 32 + pl;
    float s = 0.f, q2 = 0.f;
    for (int c = w; c < 1024; c += 8) { float v = px[c * 256]; s += v; q2 += v * v; }
    __shared__ float rs[8][32], rq[8][32];
    rs[w][pl] = s; rq[w][pl] = q2;
    __syncthreads();
    if (t < 32) {
        float S = 0.f, Q = 0.f;
        #pragma unroll
        for (int i = 0; i < 8; i++) { S += rs[i][t]; Q += rq[i][t]; }
        float mu = S * (1.f / 1024.f);
        float var = Q * (1.f / 1024.f) - mu * mu;
        g_mu[b * 256 + rp * 32 + t] = mu;
        g_rstd[b * 256 + rp * 32 + t] = rsqrtf(var + 1e-6f);
    }
}

// ---------------- K2: Q projection (bf16 3-mma) + fused offset head ----------------
__global__ void __launch_bounds__(256) k_qproj(
    const float* __restrict__ x, const float* __restrict__ lg,
    const float* __restrict__ lb, const float* __restrict__ ow1,
    const float* __restrict__ ob1, const float* __restrict__ ow2) {
    __shared__ unsigned Xh[64 * 72], Xm[64 * 72];
    __shared__ float tmp8[8];
    int ng = blockIdx.x, n = ng >> 3, g = ng & 7;
    int b = n & 63, quad = n >> 6, qh = quad >> 1, qw = quad & 1;
    int t = threadIdx.x;
    #pragma unroll 4
    for (int pass = 0; pass < 16; pass++) {
        int e = t + (pass << 8);
        int pos = e & 63, kp = e >> 6;
        int y = (qh << 3) + (pos >> 3), xx = (qw << 3) + (pos & 7);
        int cc0 = (g << 7) + 2 * kp;
        int mid = (b << 8) + y * 16 + xx;
        float mu = g_mu[mid], rstd = g_rstd[mid];
        float x0 = x[(b * 1024 + cc0) * 256 + y * 16 + xx];
        float x1 = x[(b * 1024 + cc0 + 1) * 256 + y * 16 + xx];
        float v0 = (x0 - mu) * rstd * __ldg(lg + cc0) + __ldg(lb + cc0);
        float v1 = (x1 - mu) * rstd * __ldg(lg + cc0 + 1) + __ldg(lb + cc0 + 1);
        unsigned short h0, m0v, h1, m1v;
        split_bf(v0, h0, m0v);
        split_bf(v1, h1, m1v);
        Xh[kp * 72 + pos] = (unsigned)h0 | ((unsigned)h1 << 16);
        Xm[kp * 72 + pos] = (unsigned)m0v | ((unsigned)m1v << 16);
    }
    __syncthreads();
    int lane = t & 31, w = t >> 5, gid = lane >> 2, tig = lane & 3;
    int wm = w >> 1, wn = w & 1;
    int m = wm * 16 + gid;
    const unsigned* qhp = g_wqh + (g << 12);
    const unsigned* qmp = g_wqm + (g << 12);
    float c[4][4];
    #pragma unroll
    for (int nt = 0; nt < 4; nt++) { c[nt][0] = 0.f; c[nt][1] = 0.f; c[nt][2] = 0.f; c[nt][3] = 0.f; }
    #pragma unroll
    for (int ks = 0; ks < 8; ks++) {
        int kp0 = ks * 8 + tig;
        unsigned ah[4], am[4];
        ah[0] = qhp[kp0 * 64 + m];       ah[1] = qhp[kp0 * 64 + m + 8];
        ah[2] = qhp[(kp0 + 4) * 64 + m]; ah[3] = qhp[(kp0 + 4) * 64 + m + 8];
        am[0] = qmp[kp0 * 64 + m];       am[1] = qmp[kp0 * 64 + m + 8];
        am[2] = qmp[(kp0 + 4) * 64 + m]; am[3] = qmp[(kp0 + 4) * 64 + m + 8];
        #pragma unroll
        for (int nt = 0; nt < 4; nt++) {
            int col = wn * 32 + nt * 8 + gid;
            unsigned bh0 = Xh[kp0 * 72 + col], bh1 = Xh[(kp0 + 4) * 72 + col];
            unsigned bm0 = Xm[kp0 * 72 + col], bm1 = Xm[(kp0 + 4) * 72 + col];
            mma16(c[nt], ah, bh0, bh1);
            mma16(c[nt], am, bh0, bh1);
            mma16(c[nt], ah, bm0, bm1);
        }
    }
    __syncthreads();
    float* qf = (float*)Xh;
    float* cb = (float*)Xm;
    float* qo = g_q + ng * 4096;
    #pragma unroll
    for (int nt = 0; nt < 4; nt++)
        #pragma unroll
        for (int q = 0; q < 4; q++) {
            int o = wm * 16 + gid + ((q >> 1) << 3);
            int pos = wn * 32 + nt * 8 + tig * 2 + (q & 1);
            qo[o * 64 + pos] = c[nt][q];
            qf[o * 65 + pos] = c[nt][q];
        }
    __syncthreads();
    if (t < 64) {
        float wr[36];
        #pragma unroll
        for (int u = 0; u < 36; u++) wr[u] = ow1[t * 36 + u];
        float bias = ob1[t], w2a = ow2[t], w2b = ow2[64 + t];
        #pragma unroll
        for (int sy = 0; sy < 2; sy++)
        #pragma unroll
        for (int sx = 0; sx < 2; sx++) {
            float s = bias;
            #pragma unroll
            for (int ky = 0; ky < 6; ky++) {
                int iy = sy * 4 - 1 + ky;
                if (iy < 0 || iy > 7) continue;
                #pragma unroll
                for (int kx = 0; kx < 6; kx++) {
                    int ix = sx * 4 - 1 + kx;
                    if (ix < 0 || ix > 7) continue;
                    s += wr[ky * 6 + kx] * qf[t * 65 + iy * 8 + ix];
                }
            }
            float gl = 0.5f * s * (1.f + erff(s * 0.70710678118654752f));
            cb[t * 8 + (sy * 2 + sx) * 2 + 0] = gl * w2a;
            cb[t * 8 + (sy * 2 + sx) * 2 + 1] = gl * w2b;
        }
    }
    __syncthreads();
    if (t < 8) {
        float s = 0.f;
        for (int cc = 0; cc < 64; cc++) s += cb[cc * 8 + t];
        tmp8[t] = 4.f * tanhf(s);
    }
    __syncthreads();
    if (t < 4) {
        int sy = t >> 1, sx = t & 1;
        g_vs[ng * 8 + t * 2 + 0] = 2.f * ((float)sx + tmp8[t * 2 + 0]) - 1.f;
        g_vs[ng * 8 + t * 2 + 1] = 2.f * ((float)sy + tmp8[t * 2 + 1]) - 1.f;
    }
}

// ---------------- K4: bilinear KV gather + proj (transposed weights) ----------------
__global__ void __launch_bounds__(256) k_kv(
    const float* __restrict__ x, const float* __restrict__ lg,
    const float* __restrict__ lb) {
    extern __shared__ float sm[];
    float* xp  = sm;
    float* kvs = sm + 8320;
    int ng = blockIdx.x, n = ng >> 3, g = ng & 7;
    int b = n & 63, quad = n >> 6, qh = quad >> 1, qw = quad & 1;
    int t = threadIdx.x;
    #pragma unroll 8
    for (int p = 0; p < 32; p++) {
        int idx = t + (p << 8);
        int pos = idx & 63, i = idx >> 6;
        int y = (qh << 3) + (pos >> 3), xx = (qw << 3) + (pos & 7);
        int cc = (g << 7) + i;
        float raw = x[(b * 1024 + cc) * 256 + y * 16 + xx];
        int mid = (b << 8) + y * 16 + xx;
        xp[i * 65 + pos] = (raw - g_mu[mid]) * g_rstd[mid] * __ldg(lg + cc) + __ldg(lb + cc);
    }
    __syncthreads();
    if (t < 128) {
        #pragma unroll
        for (int j = 0; j < 4; j++) {
            float vx = g_vs[ng * 8 + j * 2], vy = g_vs[ng * 8 + j * 2 + 1];
            float fx = ((vx + 1.f) * 8.f - 1.f) * 0.5f;
            float fy = ((vy + 1.f) * 8.f - 1.f) * 0.5f;
            float x0 = floorf(fx), y0 = floorf(fy);
            float wx1 = fx - x0, wy1 = fy - y0;
            float acc = 0.f;
            #pragma unroll
            for (int dy = 0; dy < 2; dy++)
            #pragma unroll
            for (int dx = 0; dx < 2; dx++) {
                float X = x0 + dx, Y = y0 + dy;
                if (X >= 0.f && X <= 7.f && Y >= 0.f && Y <= 7.f) {
                    float wgt = (dx ? wx1 : 1.f - wx1) * (dy ? wy1 : 1.f - wy1);
                    acc += wgt * xp[t * 65 + (int)Y * 8 + (int)X];
                }
            }
            kvs[t * 4 + j] = acc;
        }
    }
    __syncthreads();
    int o = t & 63, jp = (t >> 6) & 1, which = t >> 7;
    const float* wT = (which ? g_wvT : g_wkT) + (g << 13) + o;
    float a0 = 0.f, a1 = 0.f;
    #pragma unroll 8
    for (int i = 0; i < 128; i++) {
        float wt = __ldg(wT + i * 64);
        a0 += wt * kvs[i * 4 + jp];
        a1 += wt * kvs[i * 4 + jp + 2];
    }
    float* dst = (which ? g_v : g_k) + (ng << 8);
    dst[jp * 64 + o] = a0;
    dst[(jp + 2) * 64 + o] = a1;
}

// ---------------- K5: CPB MLP (R10 config: 4wm x 2wn, mh loop, 2 blocks/SM) -----
__global__ void __launch_bounds__(256, 2) k_cpb(
    const float* __restrict__ w1, const float* __restrict__ b1,
    const float* __restrict__ b2, const float* __restrict__ w3,
    const float* __restrict__ b3) {
    extern __shared__ float sm[];
    unsigned* H1p = (unsigned*)sm;
    float* w1s = sm + 17408;
    float* bx  = sm + 18176;
    float* by  = sm + 18432;
    float* part = sm + 18688;
    int ng = blockIdx.x, t = threadIdx.x;
    int lane = t & 31, w = t >> 5, gid = lane >> 2, tig = lane & 3;
    {
        w1s[t] = w1[t]; w1s[256 + t] = w1[256 + t]; w1s[512 + t] = b1[t];
        int qi = t >> 2, j = t & 3;
        float gqx = (2.f / 7.f) * (float)(qi & 7) - 1.f;
        float gqy = (2.f / 7.f) * (float)(qi >> 3) - 1.f;
        float px = gqx - g_vs[ng * 8 + j * 2], py = gqy - g_vs[ng * 8 + j * 2 + 1];
        bx[t] = copysignf(log1pf(fabsf(px)), px);
        by[t] = copysignf(log1pf(fabsf(py)), py);
    }
    int wm = w >> 1, wn = w & 1;
    float b3v = __ldg(b3);
    const uint4* wf = (const uint4*)g_w2bf;
    __syncthreads();
    for (int np = 0; np < 2; np++) {
        {
            int col = t & 127, pr0 = (t >> 7) << 6;
            float bxv = bx[np * 128 + col], byv = by[np * 128 + col];
            #pragma unroll 4
            for (int r = 0; r < 64; r++) {
                int pr = pr0 + r;
                float h0 = fmaxf(w1s[2 * pr] * bxv + w1s[256 + 2 * pr] * byv + w1s[512 + 2 * pr], 0.f);
                float h1 = fmaxf(w1s[2 * pr + 1] * bxv + w1s[256 + 2 * pr + 1] * byv + w1s[512 + 2 * pr + 1], 0.f);
                H1p[pr * 136 + col] = pack_bf2(h0, h1);
            }
        }
        __syncthreads();
        float colsum[16];
        #pragma unroll
        for (int i2 = 0; i2 < 16; i2++) colsum[i2] = 0.f;
        #pragma unroll
        for (int mh = 0; mh < 2; mh++) {
            int mb32 = wm * 2 + mh;
            int m0 = mb32 << 5;
            float c[2][8][4];
            #pragma unroll
            for (int mt = 0; mt < 2; mt++) {
                float ba = __ldg(b2 + m0 + mt * 16 + gid);
                float bb = __ldg(b2 + m0 + mt * 16 + gid + 8);
                #pragma unroll
                for (int nt = 0; nt < 8; nt++) {
                    c[mt][nt][0] = ba; c[mt][nt][1] = ba;
                    c[mt][nt][2] = bb; c[mt][nt][3] = bb;
                }
            }
            int fbase = (mb32 * 512 + lane) * 2;
            uint4 f0 = wf[fbase], f1 = wf[fbase + 1];
            for (int kc = 0; kc < 16; kc++) {
                uint4 n0, n1;
                if (kc < 15) { n0 = wf[fbase + (kc + 1) * 64]; n1 = wf[fbase + (kc + 1) * 64 + 1]; }
                unsigned a0[4] = {f0.x, f0.y, f0.z, f0.w};
                unsigned a1[4] = {f1.x, f1.y, f1.z, f1.w};
                int rb0 = (kc * 8 + tig) * 136 + (wn << 6) + gid;
                int rb1 = rb0 + 4 * 136;
                #pragma unroll
                for (int nt = 0; nt < 8; nt++) {
                    unsigned b0 = H1p[rb0 + nt * 8];
                    unsigned bv = H1p[rb1 + nt * 8];
                    mma16(c[0][nt], a0, b0, bv);
                    mma16(c[1][nt], a1, b0, bv);
                }
                if (kc < 15) { f0 = n0; f1 = n1; }
            }
            float w3r0 = __ldg(w3 + m0 + gid),      w3r1 = __ldg(w3 + m0 + gid + 8);
            float w3r2 = __ldg(w3 + m0 + 16 + gid), w3r3 = __ldg(w3 + m0 + 24 + gid);
            #pragma unroll
            for (int nt = 0; nt < 8; nt++)
                #pragma unroll
                for (int q = 0; q < 2; q++)
                    colsum[nt * 2 + q] +=
                        w3r0 * fmaxf(c[0][nt][q], 0.f) + w3r1 * fmaxf(c[0][nt][2 + q], 0.f) +
                        w3r2 * fmaxf(c[1][nt][q], 0.f) + w3r3 * fmaxf(c[1][nt][2 + q], 0.f);
        }
        #pragma unroll
        for (int off = 4; off < 32; off <<= 1)
            #pragma unroll
            for (int i2 = 0; i2 < 16; i2++)
                colsum[i2] += __shfl_xor_sync(0xffffffffu, colsum[i2], off);
        if (gid == 0) {
            #pragma unroll
            for (int i2 = 0; i2 < 16; i2++)
                part[wm * 128 + (wn << 6) + (i2 >> 1) * 8 + tig * 2 + (i2 & 1)] = colsum[i2];
        }
        __syncthreads();
        if (t < 128) {
            float s = part[t] + part[128 + t] + part[256 + t] + part[384 + t];
            g_bias[ng * 256 + np * 128 + t] = s + b3v;
        }
        __syncthreads();
    }
}

// ---------------- K6: attention (outputs packed bf16x2 hi/mid) ----------------
__global__ void __launch_bounds__(256) k_att() {
    __shared__ float qs[64][65];
    __shared__ float ks4[4][65], vs4[4][65];
    __shared__ float att_s[64][5];
    int ng = blockIdx.x, n = ng >> 3, g = ng & 7;
    int t = threadIdx.x;
    #pragma unroll
    for (int p = 0; p < 16; p++) {
        int idx = t + (p << 8);
        qs[idx >> 6][idx & 63] = g_q[ng * 4096 + idx];
    }
    { int j = t >> 6, o = t & 63; ks4[j][o] = g_k[(ng << 8) + t]; vs4[j][o] = g_v[(ng << 8) + t]; }
    __syncthreads();
    int qi = t >> 2, j = t & 3;
    float s = 0.f;
    #pragma unroll 8
    for (int d = 0; d < 64; d++) s += qs[d][qi] * ks4[j][d];
    s = s * 0.125f + g_bias[(ng << 8) + t];
    float mx = fmaxf(s, __shfl_xor_sync(0xffffffffu, s, 1));
    mx = fmaxf(mx, __shfl_xor_sync(0xffffffffu, mx, 2));
    float e = __expf(s - mx);
    float sum = e;
    sum += __shfl_xor_sync(0xffffffffu, sum, 1);
    sum += __shfl_xor_sync(0xffffffffu, sum, 2);
    att_s[qi][j] = e / sum;
    __syncthreads();
    int qi2 = t & 63, dg = t >> 6;
    float a0 = att_s[qi2][0], a1 = att_s[qi2][1], a2 = att_s[qi2][2], a3 = att_s[qi2][3];
    int ncol = (n << 6) + qi2;
    #pragma unroll
    for (int dd = 0; dd < 16; dd += 2) {
        int d = (dg << 4) + dd;
        float r0 = a0 * vs4[0][d] + a1 * vs4[1][d] + a2 * vs4[2][d] + a3 * vs4[3][d];
        float r1 = a0 * vs4[0][d + 1] + a1 * vs4[1][d + 1] + a2 * vs4[2][d + 1] + a3 * vs4[3][d + 1];
        unsigned short h0, m0v, h1, m1v;
        split_bf(r0, h0, m0v);
        split_bf(r1, h1, m1v);
        int kp = ((g << 6) + d) >> 1;
        g_atth[kp * 16384 + ncol] = (unsigned)h0 | ((unsigned)h1 << 16);
        g_attm[kp * 16384 + ncol] = (unsigned)m0v | ((unsigned)m1v << 16);
    }
}

// ---------------- K7: output projection, fully pre-packed fragments ----------------
__global__ void __launch_bounds__(256) k_out(
    const float* __restrict__ ob, float* __restrict__ out) {
    __shared__ unsigned Bh2[8 * 136], Bm2[8 * 136];
    int blk = blockIdx.x;
    int mb8 = blk & 7, nb = (blk >> 3) << 7;
    int t = threadIdx.x, lane = t & 31, w = t >> 5;
    int gid = lane >> 2, tig = lane & 3;
    int m64g = mb8 * 2 + (w >> 2);
    int nw = (w & 3) << 5;
    float c[4][4][4];
    #pragma unroll
    for (int mt = 0; mt < 4; mt++)
        #pragma unroll
        for (int nt = 0; nt < 4; nt++)
            #pragma unroll
            for (int q = 0; q < 4; q++) c[mt][nt][q] = 0.f;
    int brp = t >> 5, bcq = (t & 31) << 2;
    const uint4* athp = (const uint4*)g_atth;
    const uint4* atmp = (const uint4*)g_attm;
    const uint4* owh4 = (const uint4*)g_owfh;
    const uint4* owm4 = (const uint4*)g_owfm;
    int bbase = (brp * 16384 + nb + bcq) >> 2;   // + ck*8*16384/4 per ck
    uint4 pb_h = athp[bbase];
    uint4 pb_m = atmp[bbase];
    for (int ck = 0; ck < 32; ck++) {
        __syncthreads();
        *(uint4*)&Bh2[brp * 136 + bcq] = pb_h;
        *(uint4*)&Bm2[brp * 136 + bcq] = pb_m;
        __syncthreads();
        if (ck < 31) {
            int nxt = bbase + (ck + 1) * 32768;   // 8*16384/4
            pb_h = athp[nxt];
            pb_m = atmp[nxt];
        }
        int abase = ((m64g * 32 + ck) * 32 + lane) * 4;
        uint4 AH[4], AM[4];
        #pragma unroll
        for (int mt = 0; mt < 4; mt++) { AH[mt] = owh4[abase + mt]; AM[mt] = owm4[abase + mt]; }
        #pragma unroll
        for (int nt = 0; nt < 4; nt++) {
            int col = nw + nt * 8 + gid;
            unsigned bh0 = Bh2[tig * 136 + col], bh1 = Bh2[(tig + 4) * 136 + col];
            unsigned bm0 = Bm2[tig * 136 + col], bm1 = Bm2[(tig + 4) * 136 + col];
            #pragma unroll
            for (int mt = 0; mt < 4; mt++) {
                mma16(c[mt][nt], (unsigned*)&AH[mt], bh0, bh1);
                mma16(c[mt][nt], (unsigned*)&AM[mt], bh0, bh1);
                mma16(c[mt][nt], (unsigned*)&AH[mt], bm0, bm1);
            }
        }
    }
    #pragma unroll
    for (int mt = 0; mt < 4; mt++)
        #pragma unroll
        for (int nt = 0; nt < 4; nt++)
            #pragma unroll
            for (int q = 0; q < 4; q++) {
                int o = m64g * 64 + mt * 16 + gid + ((q >> 1) << 3);
                int col = nb + nw + nt * 8 + tig * 2 + (q & 1);
                int n = col >> 6, qi = col & 63;
                int b = n & 63, quad = n >> 6;
                int y = ((quad >> 1) << 3) + (qi >> 3);
                int xx = ((quad & 1) << 3) + (qi & 7);
                out[((b * 1024 + o) * 16 + y) * 16 + xx] = c[mt][nt][q] + __ldg(ob + o);
            }
}

extern "C" void kernel_launch(void* const* d_in, const int* in_sizes, int n_in,
                              void* d_out, int out_size) {
    const float* x      = (const float*)d_in[0];
    const float* ln_g   = (const float*)d_in[1];
    const float* ln_b   = (const float*)d_in[2];
    const float* wq     = (const float*)d_in[3];
    const float* wk     = (const float*)d_in[4];
    const float* wv     = (const float*)d_in[5];
    const float* off_w1 = (const float*)d_in[6];
    const float* off_b1 = (const float*)d_in[7];
    const float* off_w2 = (const float*)d_in[8];
    const float* cpb_w1 = (const float*)d_in[9];
    const float* cpb_b1 = (const float*)d_in[10];
    const float* cpb_w2 = (const float*)d_in[11];
    const float* cpb_b2 = (const float*)d_in[12];
    const float* cpb_w3 = (const float*)d_in[13];
    const float* cpb_b3 = (const float*)d_in[14];
    const float* out_w  = (const float*)d_in[15];
    const float* out_b  = (const float*)d_in[16];
    float* out = (float*)d_out;
    const int KV_SMEM  = 8832 * 4;    // 35328 B
    const int CPB_SMEM = 19200 * 4;   // 76800 B (2 blocks/SM)
    cudaFuncSetAttribute(k_kv,  cudaFuncAttributeMaxDynamicSharedMemorySize, KV_SMEM);
    cudaFuncSetAttribute(k_cpb, cudaFuncAttributeMaxDynamicSharedMemorySize, CPB_SMEM);
    k_ln<<<512, 256>>>(x, cpb_w2, wq, wk, wv, out_w);
    k_qproj<<<2048, 256>>>(x, ln_g, ln_b, off_w1, off_b1, off_w2);
    k_cpb<<<2048, 256, CPB_SMEM>>>(cpb_w1, cpb_b1, cpb_b2, cpb_w3, cpb_b3);
    k_kv<<<2048, 256, KV_SMEM>>>(x, ln_g, ln_b);
    k_att<<<2048, 256>>>();
    k_out<<<1024, 256>>>(out_b, out);
}

// round 17
// speedup vs baseline: 1.2258x; 1.0303x over previous
#include <cuda_runtime.h>
#include <cuda_bf16.h>
#include <cuda_fp16.h>
#include <math.h>

#define DEVI __device__ __forceinline__

__device__ float g_mu[16384];
__device__ float g_rstd[16384];
__device__ float g_q[2048 * 4096];     // [ng][o][pos]
__device__ float g_vs[2048 * 8];       // [ng][j][x,y]
__device__ float g_bias[2048 * 256];   // [ng][qi*4+j]
__device__ unsigned g_atth[256 * 16384]; // attention out, fp16x2 (pair-packed), [kp][col]
__device__ unsigned g_w2bf[32768];     // fragment-ordered bf16x2 of cpb_w2
__device__ unsigned g_wqh[32768];      // wq hi  bf16x2: [g][kp=64][m=64]
__device__ unsigned g_wqm[32768];      // wq mid bf16x2
__device__ float g_wkT[65536];         // wk transposed [g][i=128][o=64]
__device__ float g_wvT[65536];         // wv transposed
__device__ unsigned g_owfh[262144];    // out_w frag-packed fp16 hi  (16 m64g x 32 ck x 32 lane x 4 mt) uint4
__device__ unsigned g_owfm[262144];    // out_w frag-packed fp16 mid

DEVI void mma16(float* c, const unsigned* a, unsigned b0, unsigned b1) {
    asm("mma.sync.aligned.m16n8k16.row.col.f32.bf16.bf16.f32 "
        "{%0,%1,%2,%3}, {%4,%5,%6,%7}, {%8,%9}, {%0,%1,%2,%3};"
        : "+f"(c[0]), "+f"(c[1]), "+f"(c[2]), "+f"(c[3])
        : "r"(a[0]), "r"(a[1]), "r"(a[2]), "r"(a[3]), "r"(b0), "r"(b1));
}
DEVI void mma16h(float* c, const unsigned* a, unsigned b0, unsigned b1) {
    asm("mma.sync.aligned.m16n8k16.row.col.f32.f16.f16.f32 "
        "{%0,%1,%2,%3}, {%4,%5,%6,%7}, {%8,%9}, {%0,%1,%2,%3};"
        : "+f"(c[0]), "+f"(c[1]), "+f"(c[2]), "+f"(c[3])
        : "r"(a[0]), "r"(a[1]), "r"(a[2]), "r"(a[3]), "r"(b0), "r"(b1));
}
DEVI unsigned pack_bf2(float lo, float hi) {
    unsigned a = (unsigned)__bfloat16_as_ushort(__float2bfloat16_rn(lo));
    unsigned b = (unsigned)__bfloat16_as_ushort(__float2bfloat16_rn(hi));
    return a | (b << 16);
}
DEVI void split_bf(float v, unsigned short& h, unsigned short& m) {
    __nv_bfloat16 bh = __float2bfloat16_rn(v);
    float hv = __bfloat162float(bh);
    h = __bfloat16_as_ushort(bh);
    m = __bfloat16_as_ushort(__float2bfloat16_rn(v - hv));
}
DEVI unsigned hf_sel(float v, int mid) {
    __half hh = __float2half_rn(v);
    if (!mid) return (unsigned)__half_as_ushort(hh);
    return (unsigned)__half_as_ushort(__float2half_rn(v - __half2float(hh)));
}
DEVI unsigned pack_hf2(float lo, float hi) {
    unsigned a = (unsigned)__half_as_ushort(__float2half_rn(lo));
    unsigned b = (unsigned)__half_as_ushort(__float2half_rn(hi));
    return a | (b << 16);
}

// ---------------- K1: LayerNorm stats + weight packing/transposes ----------------
__global__ void __launch_bounds__(256) k_ln(const float* __restrict__ x,
                                           const float* __restrict__ w2,
                                           const float* __restrict__ wq,
                                           const float* __restrict__ wk,
                                           const float* __restrict__ wv,
                                           const float* __restrict__ ow) {
    int fi = blockIdx.x * 256 + threadIdx.x;
    if (fi < 32768) {
        int u = fi & 7, lane = (fi >> 3) & 31, kc = (fi >> 8) & 15, mb32 = fi >> 12;
        int tig = lane & 3, gid = lane >> 2;
        int mt = u >> 2, q = u & 3;
        int k2 = kc * 8 + tig + ((q & 2) ? 4 : 0);
        int m = mb32 * 32 + mt * 16 + gid + ((q & 1) ? 8 : 0);
        g_w2bf[fi] = pack_bf2(w2[(2 * k2) * 256 + m], w2[(2 * k2 + 1) * 256 + m]);
        int g = fi >> 12, kp = (fi >> 6) & 63, m2 = fi & 63;
        float v0 = wq[g * 8192 + m2 * 128 + 2 * kp];
        float v1 = wq[g * 8192 + m2 * 128 + 2 * kp + 1];
        unsigned short h0, mm0, h1, mm1;
        split_bf(v0, h0, mm0);
        split_bf(v1, h1, mm1);
        g_wqh[fi] = (unsigned)h0 | ((unsigned)h1 << 16);
        g_wqm[fi] = (unsigned)mm0 | ((unsigned)mm1 << 16);
    }
    if (fi < 65536) {
        int g = fi >> 13, i = (fi >> 6) & 127, o = fi & 63;
        g_wkT[fi] = wk[g * 8192 + o * 128 + i];
        g_wvT[fi] = wv[g * 8192 + o * 128 + i];
    }
    {   // out_w fragment packing (fp16 hi/mid): fi covers 131072 exactly
        int u = fi & 7, lane = (fi >> 3) & 31, ck = (fi >> 8) & 31, m64g = fi >> 13;
        int tig = lane & 3, gid = lane >> 2;
        int mt = u & 3, ish = u >> 2;
        int kp = ck * 8 + tig;
        int m = m64g * 64 + mt * 16 + gid;
        unsigned j0 = hf_sel(ow[m * 512 + 2 * kp], ish)
                    | (hf_sel(ow[m * 512 + 2 * kp + 1], ish) << 16);
        unsigned j1 = hf_sel(ow[(m + 8) * 512 + 2 * kp], ish)
                    | (hf_sel(ow[(m + 8) * 512 + 2 * kp + 1], ish) << 16);
        unsigned j2 = hf_sel(ow[m * 512 + 2 * (kp + 4)], ish)
                    | (hf_sel(ow[m * 512 + 2 * (kp + 4) + 1], ish) << 16);
        unsigned j3 = hf_sel(ow[(m + 8) * 512 + 2 * (kp + 4)], ish)
                    | (hf_sel(ow[(m + 8) * 512 + 2 * (kp + 4) + 1], ish) << 16);
        int oidx = ((m64g * 32 + ck) * 32 + lane) * 4 + mt;
        uint4 v4 = make_uint4(j0, j1, j2, j3);
        if (ish == 0) ((uint4*)g_owfh)[oidx] = v4;
        else          ((uint4*)g_owfm)[oidx] = v4;
    }
    int b = blockIdx.x >> 3, rp = blockIdx.x & 7;
    int t = threadIdx.x, pl = t & 31, w = t >> 5;
    const float* px = x + b * 262144 + rp * 32 + pl;
    float s = 0.f, q2 = 0.f;
    for (int c = w; c < 1024; c += 8) { float v = px[c * 256]; s += v; q2 += v * v; }
    __shared__ float rs[8][32], rq[8][32];
    rs[w][pl] = s; rq[w][pl] = q2;
    __syncthreads();
    if (t < 32) {
        float S = 0.f, Q = 0.f;
        #pragma unroll
        for (int i = 0; i < 8; i++) { S += rs[i][t]; Q += rq[i][t]; }
        float mu = S * (1.f / 1024.f);
        float var = Q * (1.f / 1024.f) - mu * mu;
        g_mu[b * 256 + rp * 32 + t] = mu;
        g_rstd[b * 256 + rp * 32 + t] = rsqrtf(var + 1e-6f);
    }
}

// ---------------- K2: Q projection (bf16 3-mma) + fused offset head ----------------
__global__ void __launch_bounds__(256) k_qproj(
    const float* __restrict__ x, const float* __restrict__ lg,
    const float* __restrict__ lb, const float* __restrict__ ow1,
    const float* __restrict__ ob1, const float* __restrict__ ow2) {
    __shared__ unsigned Xh[64 * 72], Xm[64 * 72];
    __shared__ float tmp8[8];
    int ng = blockIdx.x, n = ng >> 3, g = ng & 7;
    int b = n & 63, quad = n >> 6, qh = quad >> 1, qw = quad & 1;
    int t = threadIdx.x;
    #pragma unroll 4
    for (int pass = 0; pass < 16; pass++) {
        int e = t + (pass << 8);
        int pos = e & 63, kp = e >> 6;
        int y = (qh << 3) + (pos >> 3), xx = (qw << 3) + (pos & 7);
        int cc0 = (g << 7) + 2 * kp;
        int mid = (b << 8) + y * 16 + xx;
        float mu = g_mu[mid], rstd = g_rstd[mid];
        float x0 = x[(b * 1024 + cc0) * 256 + y * 16 + xx];
        float x1 = x[(b * 1024 + cc0 + 1) * 256 + y * 16 + xx];
        float v0 = (x0 - mu) * rstd * __ldg(lg + cc0) + __ldg(lb + cc0);
        float v1 = (x1 - mu) * rstd * __ldg(lg + cc0 + 1) + __ldg(lb + cc0 + 1);
        unsigned short h0, m0v, h1, m1v;
        split_bf(v0, h0, m0v);
        split_bf(v1, h1, m1v);
        Xh[kp * 72 + pos] = (unsigned)h0 | ((unsigned)h1 << 16);
        Xm[kp * 72 + pos] = (unsigned)m0v | ((unsigned)m1v << 16);
    }
    __syncthreads();
    int lane = t & 31, w = t >> 5, gid = lane >> 2, tig = lane & 3;
    int wm = w >> 1, wn = w & 1;
    int m = wm * 16 + gid;
    const unsigned* qhp = g_wqh + (g << 12);
    const unsigned* qmp = g_wqm + (g << 12);
    float c[4][4];
    #pragma unroll
    for (int nt = 0; nt < 4; nt++) { c[nt][0] = 0.f; c[nt][1] = 0.f; c[nt][2] = 0.f; c[nt][3] = 0.f; }
    #pragma unroll
    for (int ks = 0; ks < 8; ks++) {
        int kp0 = ks * 8 + tig;
        unsigned ah[4], am[4];
        ah[0] = qhp[kp0 * 64 + m];       ah[1] = qhp[kp0 * 64 + m + 8];
        ah[2] = qhp[(kp0 + 4) * 64 + m]; ah[3] = qhp[(kp0 + 4) * 64 + m + 8];
        am[0] = qmp[kp0 * 64 + m];       am[1] = qmp[kp0 * 64 + m + 8];
        am[2] = qmp[(kp0 + 4) * 64 + m]; am[3] = qmp[(kp0 + 4) * 64 + m + 8];
        #pragma unroll
        for (int nt = 0; nt < 4; nt++) {
            int col = wn * 32 + nt * 8 + gid;
            unsigned bh0 = Xh[kp0 * 72 + col], bh1 = Xh[(kp0 + 4) * 72 + col];
            unsigned bm0 = Xm[kp0 * 72 + col], bm1 = Xm[(kp0 + 4) * 72 + col];
            mma16(c[nt], ah, bh0, bh1);
            mma16(c[nt], am, bh0, bh1);
            mma16(c[nt], ah, bm0, bm1);
        }
    }
    __syncthreads();
    float* qf = (float*)Xh;
    float* cb = (float*)Xm;
    float* qo = g_q + ng * 4096;
    #pragma unroll
    for (int nt = 0; nt < 4; nt++)
        #pragma unroll
        for (int q = 0; q < 4; q++) {
            int o = wm * 16 + gid + ((q >> 1) << 3);
            int pos = wn * 32 + nt * 8 + tig * 2 + (q & 1);
            qo[o * 64 + pos] = c[nt][q];
            qf[o * 65 + pos] = c[nt][q];
        }
    __syncthreads();
    if (t < 64) {
        float wr[36];
        #pragma unroll
        for (int u = 0; u < 36; u++) wr[u] = ow1[t * 36 + u];
        float bias = ob1[t], w2a = ow2[t], w2b = ow2[64 + t];
        #pragma unroll
        for (int sy = 0; sy < 2; sy++)
        #pragma unroll
        for (int sx = 0; sx < 2; sx++) {
            float s = bias;
            #pragma unroll
            for (int ky = 0; ky < 6; ky++) {
                int iy = sy * 4 - 1 + ky;
                if (iy < 0 || iy > 7) continue;
                #pragma unroll
                for (int kx = 0; kx < 6; kx++) {
                    int ix = sx * 4 - 1 + kx;
                    if (ix < 0 || ix > 7) continue;
                    s += wr[ky * 6 + kx] * qf[t * 65 + iy * 8 + ix];
                }
            }
            float gl = 0.5f * s * (1.f + erff(s * 0.70710678118654752f));
            cb[t * 8 + (sy * 2 + sx) * 2 + 0] = gl * w2a;
            cb[t * 8 + (sy * 2 + sx) * 2 + 1] = gl * w2b;
        }
    }
    __syncthreads();
    if (t < 8) {
        float s = 0.f;
        for (int cc = 0; cc < 64; cc++) s += cb[cc * 8 + t];
        tmp8[t] = 4.f * tanhf(s);
    }
    __syncthreads();
    if (t < 4) {
        int sy = t >> 1, sx = t & 1;
        g_vs[ng * 8 + t * 2 + 0] = 2.f * ((float)sx + tmp8[t * 2 + 0]) - 1.f;
        g_vs[ng * 8 + t * 2 + 1] = 2.f * ((float)sy + tmp8[t * 2 + 1]) - 1.f;
    }
}

// ---------------- K5: CPB MLP (unchanged R10 config) ----------------
__global__ void __launch_bounds__(256, 2) k_cpb(
    const float* __restrict__ w1, const float* __restrict__ b1,
    const float* __restrict__ b2, const float* __restrict__ w3,
    const float* __restrict__ b3) {
    extern __shared__ float sm[];
    unsigned* H1p = (unsigned*)sm;
    float* w1s = sm + 17408;
    float* bx  = sm + 18176;
    float* by  = sm + 18432;
    float* part = sm + 18688;
    int ng = blockIdx.x, t = threadIdx.x;
    int lane = t & 31, w = t >> 5, gid = lane >> 2, tig = lane & 3;
    {
        w1s[t] = w1[t]; w1s[256 + t] = w1[256 + t]; w1s[512 + t] = b1[t];
        int qi = t >> 2, j = t & 3;
        float gqx = (2.f / 7.f) * (float)(qi & 7) - 1.f;
        float gqy = (2.f / 7.f) * (float)(qi >> 3) - 1.f;
        float px = gqx - g_vs[ng * 8 + j * 2], py = gqy - g_vs[ng * 8 + j * 2 + 1];
        bx[t] = copysignf(log1pf(fabsf(px)), px);
        by[t] = copysignf(log1pf(fabsf(py)), py);
    }
    int wm = w >> 1, wn = w & 1;
    float b3v = __ldg(b3);
    const uint4* wf = (const uint4*)g_w2bf;
    __syncthreads();
    for (int np = 0; np < 2; np++) {
        {
            int col = t & 127, pr0 = (t >> 7) << 6;
            float bxv = bx[np * 128 + col], byv = by[np * 128 + col];
            #pragma unroll 4
            for (int r = 0; r < 64; r++) {
                int pr = pr0 + r;
                float h0 = fmaxf(w1s[2 * pr] * bxv + w1s[256 + 2 * pr] * byv + w1s[512 + 2 * pr], 0.f);
                float h1 = fmaxf(w1s[2 * pr + 1] * bxv + w1s[256 + 2 * pr + 1] * byv + w1s[512 + 2 * pr + 1], 0.f);
                H1p[pr * 136 + col] = pack_bf2(h0, h1);
            }
        }
        __syncthreads();
        float colsum[16];
        #pragma unroll
        for (int i2 = 0; i2 < 16; i2++) colsum[i2] = 0.f;
        #pragma unroll
        for (int mh = 0; mh < 2; mh++) {
            int mb32 = wm * 2 + mh;
            int m0 = mb32 << 5;
            float c[2][8][4];
            #pragma unroll
            for (int mt = 0; mt < 2; mt++) {
                float ba = __ldg(b2 + m0 + mt * 16 + gid);
                float bb = __ldg(b2 + m0 + mt * 16 + gid + 8);
                #pragma unroll
                for (int nt = 0; nt < 8; nt++) {
                    c[mt][nt][0] = ba; c[mt][nt][1] = ba;
                    c[mt][nt][2] = bb; c[mt][nt][3] = bb;
                }
            }
            int fbase = (mb32 * 512 + lane) * 2;
            uint4 f0 = wf[fbase], f1 = wf[fbase + 1];
            for (int kc = 0; kc < 16; kc++) {
                uint4 n0, n1;
                if (kc < 15) { n0 = wf[fbase + (kc + 1) * 64]; n1 = wf[fbase + (kc + 1) * 64 + 1]; }
                unsigned a0[4] = {f0.x, f0.y, f0.z, f0.w};
                unsigned a1[4] = {f1.x, f1.y, f1.z, f1.w};
                int rb0 = (kc * 8 + tig) * 136 + (wn << 6) + gid;
                int rb1 = rb0 + 4 * 136;
                #pragma unroll
                for (int nt = 0; nt < 8; nt++) {
                    unsigned b0 = H1p[rb0 + nt * 8];
                    unsigned bv = H1p[rb1 + nt * 8];
                    mma16(c[0][nt], a0, b0, bv);
                    mma16(c[1][nt], a1, b0, bv);
                }
                if (kc < 15) { f0 = n0; f1 = n1; }
            }
            float w3r0 = __ldg(w3 + m0 + gid),      w3r1 = __ldg(w3 + m0 + gid + 8);
            float w3r2 = __ldg(w3 + m0 + 16 + gid), w3r3 = __ldg(w3 + m0 + 24 + gid);
            #pragma unroll
            for (int nt = 0; nt < 8; nt++)
                #pragma unroll
                for (int q = 0; q < 2; q++)
                    colsum[nt * 2 + q] +=
                        w3r0 * fmaxf(c[0][nt][q], 0.f) + w3r1 * fmaxf(c[0][nt][2 + q], 0.f) +
                        w3r2 * fmaxf(c[1][nt][q], 0.f) + w3r3 * fmaxf(c[1][nt][2 + q], 0.f);
        }
        #pragma unroll
        for (int off = 4; off < 32; off <<= 1)
            #pragma unroll
            for (int i2 = 0; i2 < 16; i2++)
                colsum[i2] += __shfl_xor_sync(0xffffffffu, colsum[i2], off);
        if (gid == 0) {
            #pragma unroll
            for (int i2 = 0; i2 < 16; i2++)
                part[wm * 128 + (wn << 6) + (i2 >> 1) * 8 + tig * 2 + (i2 & 1)] = colsum[i2];
        }
        __syncthreads();
        if (t < 128) {
            float s = part[t] + part[128 + t] + part[256 + t] + part[384 + t];
            g_bias[ng * 256 + np * 128 + t] = s + b3v;
        }
        __syncthreads();
    }
}

// ---------------- K4: fused KV gather/proj + attention (k/v never leave smem) ----
// dyn smem floats: xp @0 (8320) | kvs @8320 (512) | qs @8832 (4160) |
// ks4 @12992 (260) | vs4 @13252 (260) | att_s @13512 (325) -> 13840 fl = 55360 B
__global__ void __launch_bounds__(256) k_kvatt(
    const float* __restrict__ x, const float* __restrict__ lg,
    const float* __restrict__ lb) {
    extern __shared__ float sm[];
    float* xp    = sm;
    float* kvs   = sm + 8320;
    float* qs    = sm + 8832;
    float* ks4   = sm + 12992;
    float* vs4   = sm + 13252;
    float* att_s = sm + 13512;
    int ng = blockIdx.x, n = ng >> 3, g = ng & 7;
    int b = n & 63, quad = n >> 6, qh = quad >> 1, qw = quad & 1;
    int t = threadIdx.x;
    #pragma unroll 8
    for (int p = 0; p < 32; p++) {
        int idx = t + (p << 8);
        int pos = idx & 63, i = idx >> 6;
        int y = (qh << 3) + (pos >> 3), xx = (qw << 3) + (pos & 7);
        int cc = (g << 7) + i;
        float raw = x[(b * 1024 + cc) * 256 + y * 16 + xx];
        int mid = (b << 8) + y * 16 + xx;
        xp[i * 65 + pos] = (raw - g_mu[mid]) * g_rstd[mid] * __ldg(lg + cc) + __ldg(lb + cc);
    }
    #pragma unroll 4
    for (int p = 0; p < 16; p++) {
        int idx = t + (p << 8);
        qs[(idx >> 6) * 65 + (idx & 63)] = g_q[ng * 4096 + idx];
    }
    __syncthreads();
    if (t < 128) {
        #pragma unroll
        for (int j = 0; j < 4; j++) {
            float vx = g_vs[ng * 8 + j * 2], vy = g_vs[ng * 8 + j * 2 + 1];
            float fx = ((vx + 1.f) * 8.f - 1.f) * 0.5f;
            float fy = ((vy + 1.f) * 8.f - 1.f) * 0.5f;
            float x0 = floorf(fx), y0 = floorf(fy);
            float wx1 = fx - x0, wy1 = fy - y0;
            float acc = 0.f;
            #pragma unroll
            for (int dy = 0; dy < 2; dy++)
            #pragma unroll
            for (int dx = 0; dx < 2; dx++) {
                float X = x0 + dx, Y = y0 + dy;
                if (X >= 0.f && X <= 7.f && Y >= 0.f && Y <= 7.f) {
                    float wgt = (dx ? wx1 : 1.f - wx1) * (dy ? wy1 : 1.f - wy1);
                    acc += wgt * xp[t * 65 + (int)Y * 8 + (int)X];
                }
            }
            kvs[t * 4 + j] = acc;
        }
    }
    __syncthreads();
    {
        int o = t & 63, jp = (t >> 6) & 1, which = t >> 7;
        const float* wT = (which ? g_wvT : g_wkT) + (g << 13) + o;
        float a0 = 0.f, a1 = 0.f;
        #pragma unroll 8
        for (int i = 0; i < 128; i++) {
            float wt = __ldg(wT + i * 64);
            a0 += wt * kvs[i * 4 + jp];
            a1 += wt * kvs[i * 4 + jp + 2];
        }
        float* dst = which ? vs4 : ks4;
        dst[jp * 65 + o] = a0;
        dst[(jp + 2) * 65 + o] = a1;
    }
    __syncthreads();
    {
        int qi = t >> 2, j = t & 3;
        float s = 0.f;
        #pragma unroll 8
        for (int d = 0; d < 64; d++) s += qs[d * 65 + qi] * ks4[j * 65 + d];
        s = s * 0.125f + g_bias[(ng << 8) + t];
        float mx = fmaxf(s, __shfl_xor_sync(0xffffffffu, s, 1));
        mx = fmaxf(mx, __shfl_xor_sync(0xffffffffu, mx, 2));
        float e = __expf(s - mx);
        float sum = e;
        sum += __shfl_xor_sync(0xffffffffu, sum, 1);
        sum += __shfl_xor_sync(0xffffffffu, sum, 2);
        att_s[qi * 5 + j] = e / sum;
    }
    __syncthreads();
    {
        int qi2 = t & 63, dg = t >> 6;
        float a0 = att_s[qi2 * 5 + 0], a1 = att_s[qi2 * 5 + 1];
        float a2 = att_s[qi2 * 5 + 2], a3 = att_s[qi2 * 5 + 3];
        int ncol = (n << 6) + qi2;
        #pragma unroll
        for (int dd = 0; dd < 16; dd += 2) {
            int d = (dg << 4) + dd;
            float r0 = a0 * vs4[0 * 65 + d] + a1 * vs4[1 * 65 + d] + a2 * vs4[2 * 65 + d] + a3 * vs4[3 * 65 + d];
            float r1 = a0 * vs4[0 * 65 + d + 1] + a1 * vs4[1 * 65 + d + 1] + a2 * vs4[2 * 65 + d + 1] + a3 * vs4[3 * 65 + d + 1];
            int kp = ((g << 6) + d) >> 1;
            g_atth[kp * 16384 + ncol] = pack_hf2(r0, r1);
        }
    }
}

// ---------------- K7: output projection, fp16 2-mma (A hi+mid, B hi) ----------------
__global__ void __launch_bounds__(256) k_out(
    const float* __restrict__ ob, float* __restrict__ out) {
    __shared__ unsigned Bh2[8 * 136];
    int blk = blockIdx.x;
    int mb8 = blk & 7, nb = (blk >> 3) << 7;
    int t = threadIdx.x, lane = t & 31, w = t >> 5;
    int gid = lane >> 2, tig = lane & 3;
    int m64g = mb8 * 2 + (w >> 2);
    int nw = (w & 3) << 5;
    float c[4][4][4];
    #pragma unroll
    for (int mt = 0; mt < 4; mt++)
        #pragma unroll
        for (int nt = 0; nt < 4; nt++)
            #pragma unroll
            for (int q = 0; q < 4; q++) c[mt][nt][q] = 0.f;
    int brp = t >> 5, bcq = (t & 31) << 2;
    const uint4* athp = (const uint4*)g_atth;
    const uint4* owh4 = (const uint4*)g_owfh;
    const uint4* owm4 = (const uint4*)g_owfm;
    int bbase = (brp * 16384 + nb + bcq) >> 2;
    uint4 pb_h = athp[bbase];
    for (int ck = 0; ck < 32; ck++) {
        __syncthreads();
        *(uint4*)&Bh2[brp * 136 + bcq] = pb_h;
        __syncthreads();
        if (ck < 31) pb_h = athp[bbase + (ck + 1) * 32768];
        int abase = ((m64g * 32 + ck) * 32 + lane) * 4;
        uint4 AH[4], AM[4];
        #pragma unroll
        for (int mt = 0; mt < 4; mt++) { AH[mt] = owh4[abase + mt]; AM[mt] = owm4[abase + mt]; }
        #pragma unroll
        for (int nt = 0; nt < 4; nt++) {
            int col = nw + nt * 8 + gid;
            unsigned bh0 = Bh2[tig * 136 + col], bh1 = Bh2[(tig + 4) * 136 + col];
            #pragma unroll
            for (int mt = 0; mt < 4; mt++) {
                mma16h(c[mt][nt], (unsigned*)&AH[mt], bh0, bh1);
                mma16h(c[mt][nt], (unsigned*)&AM[mt], bh0, bh1);
            }
        }
    }
    #pragma unroll
    for (int mt = 0; mt < 4; mt++)
        #pragma unroll
        for (int nt = 0; nt < 4; nt++)
            #pragma unroll
            for (int q = 0; q < 4; q++) {
                int o = m64g * 64 + mt * 16 + gid + ((q >> 1) << 3);
                int col = nb + nw + nt * 8 + tig * 2 + (q & 1);
                int n = col >> 6, qi = col & 63;
                int b = n & 63, quad = n >> 6;
                int y = ((quad >> 1) << 3) + (qi >> 3);
                int xx = ((quad & 1) << 3) + (qi & 7);
                out[((b * 1024 + o) * 16 + y) * 16 + xx] = c[mt][nt][q] + __ldg(ob + o);
            }
}

extern "C" void kernel_launch(void* const* d_in, const int* in_sizes, int n_in,
                              void* d_out, int out_size) {
    const float* x      = (const float*)d_in[0];
    const float* ln_g   = (const float*)d_in[1];
    const float* ln_b   = (const float*)d_in[2];
    const float* wq     = (const float*)d_in[3];
    const float* wk     = (const float*)d_in[4];
    const float* wv     = (const float*)d_in[5];
    const float* off_w1 = (const float*)d_in[6];
    const float* off_b1 = (const float*)d_in[7];
    const float* off_w2 = (const float*)d_in[8];
    const float* cpb_w1 = (const float*)d_in[9];
    const float* cpb_b1 = (const float*)d_in[10];
    const float* cpb_w2 = (const float*)d_in[11];
    const float* cpb_b2 = (const float*)d_in[12];
    const float* cpb_w3 = (const float*)d_in[13];
    const float* cpb_b3 = (const float*)d_in[14];
    const float* out_w  = (const float*)d_in[15];
    const float* out_b  = (const float*)d_in[16];
    float* out = (float*)d_out;
    const int KVA_SMEM = 13840 * 4;   // 55360 B
    const int CPB_SMEM = 19200 * 4;   // 76800 B (2 blocks/SM)
    cudaFuncSetAttribute(k_kvatt, cudaFuncAttributeMaxDynamicSharedMemorySize, KVA_SMEM);
    cudaFuncSetAttribute(k_cpb,   cudaFuncAttributeMaxDynamicSharedMemorySize, CPB_SMEM);
    k_ln<<<512, 256>>>(x, cpb_w2, wq, wk, wv, out_w);
    k_qproj<<<2048, 256>>>(x, ln_g, ln_b, off_w1, off_b1, off_w2);
    k_cpb<<<2048, 256, CPB_SMEM>>>(cpb_w1, cpb_b1, cpb_b2, cpb_w3, cpb_b3);
    k_kvatt<<<2048, 256, KVA_SMEM>>>(x, ln_g, ln_b);
    k_out<<<1024, 256>>>(out_b, out);
}